// round 15
// baseline (speedup 1.0000x reference)
#include <cuda_runtime.h>
#include <cuda_bf16.h>
#include <math.h>

#define B_  2048
#define L_  200
#define C_  100
#define V_  2000

// ---------------- scratch ----------------
__device__ float g_IG  [B_*5*384];
__device__ float g_CT  [B_*128];
__device__ float g_CI  [B_*128];
__device__ float g_AL  [B_*3];
__device__ float g_WIHf[73728];        // W_ih (N=384,K=192) tf32 frag order
__device__ float g_WHHf[49152];        // W_hh (N=384,K=128) tf32 frag order
__device__ float g_WCT [32768];        // [Wt1 src | Wt1 h]  (N=128,K=256) tf32 frag
__device__ float g_WCI [24576];        // [Wi1 src | Wi1 h]  (N=128,K=192) tf32 frag
__device__ float g_WA  [8192];         // Wa1 (N=64,K=128) tf32 frag
__device__ unsigned g_WT16[8192];      // Wt1 mid slab bf16 m16n8k16 frag (32KB)
__device__ unsigned g_WI16[4096];      // Wi1 mid slab bf16 m16n8k16 frag (16KB)
__device__ int   g_LI  [B_];

__device__ __forceinline__ float sigf(float x){ return 1.0f/(1.0f+__expf(-x)); }
__device__ __forceinline__ float tanhf_fast(float x){
  x = fminf(fmaxf(x,-15.f),15.f);
  float e = __expf(2.f*x);
  return (e-1.f)/(e+1.f);
}
__device__ __forceinline__ float wsum(float v){
#pragma unroll
  for (int o=16;o;o>>=1) v += __shfl_xor_sync(0xffffffffu, v, o);
  return v;
}
__device__ __forceinline__ float wmax(float v){
#pragma unroll
  for (int o=16;o;o>>=1) v = fmaxf(v, __shfl_xor_sync(0xffffffffu, v, o));
  return v;
}
__device__ __forceinline__ unsigned f2tf(float x){
  unsigned r; asm("cvt.rna.tf32.f32 %0, %1;" : "=r"(r) : "f"(x)); return r;
}
__device__ __forceinline__ unsigned pkbf(float lo, float hi){
  __nv_bfloat162 h = __floats2bfloat162_rn(lo, hi);
  return *(unsigned*)&h;
}
__device__ __forceinline__ void mma8(float* d,
    unsigned a0, unsigned a1, unsigned a2, unsigned a3,
    unsigned b0, unsigned b1){
  asm volatile(
    "mma.sync.aligned.m16n8k8.row.col.f32.tf32.tf32.f32 "
    "{%0,%1,%2,%3},{%4,%5,%6,%7},{%8,%9},{%0,%1,%2,%3};\n"
    : "+f"(d[0]),"+f"(d[1]),"+f"(d[2]),"+f"(d[3])
    : "r"(a0),"r"(a1),"r"(a2),"r"(a3),"r"(b0),"r"(b1));
}
__device__ __forceinline__ void mma16(float* d,
    unsigned a0, unsigned a1, unsigned a2, unsigned a3,
    unsigned b0, unsigned b1){
  asm volatile(
    "mma.sync.aligned.m16n8k16.row.col.f32.bf16.bf16.f32 "
    "{%0,%1,%2,%3},{%4,%5,%6,%7},{%8,%9},{%0,%1,%2,%3};\n"
    : "+f"(d[0]),"+f"(d[1]),"+f"(d[2]),"+f"(d[3])
    : "r"(a0),"r"(a1),"r"(a2),"r"(a3),"r"(b0),"r"(b1));
}

// decode tf32 fragment-order flat index -> (j,k) for weight W[N][K]
__device__ __forceinline__ void frag_jk(int idx, int N, int* jj, int* kk){
  int c = idx & 3, lane = (idx>>2)&31;
  int P = N >> 4;
  int pr = (idx>>7) % P;
  int kt = idx / (128*P);
  int nt = 2*pr + (c>>1), p = c&1;
  *jj = nt*8 + (lane>>2);
  *kk = kt*8 + (lane&3) + 4*p;
}
// decode bf16 m16n8k16 frag (uint4-of-n-pairs) flat uint index -> (j, k0)
__device__ __forceinline__ void frag16_jk(int idx, int* jj, int* kk){
  int w = idx & 3, lane = (idx>>2)&31, n2 = (idx>>7)&7, kt = idx>>10;
  int n = 2*n2 + (w>>1);
  *jj = n*8 + (lane>>2);
  *kk = kt*16 + (lane&3)*2 + (w&1)*8;
}

// ---- prepare all fragment-ordered weights ----
__global__ void k_wprep(const float* __restrict__ Wih, const float* __restrict__ Whh,
                        const float* __restrict__ Wt1, const float* __restrict__ Wi1,
                        const float* __restrict__ Wa1){
  int idx = blockIdx.x*blockDim.x + threadIdx.x;
  int j, k;
  int off = 0;
  if (idx < (off += 73728)){                       // Wih: N=384,K=192
    frag_jk(idx, 384, &j, &k);
    g_WIHf[idx] = __uint_as_float(f2tf(Wih[(long)j*192 + k]));
    return;
  }
  if (idx < (off + 49152)){                        // Whh: N=384,K=128
    int i2 = idx - off;
    frag_jk(i2, 384, &j, &k);
    g_WHHf[i2] = __uint_as_float(f2tf(Whh[(long)j*128 + k]));
    return;
  }
  off += 49152;
  if (idx < (off + 32768)){                        // WCT: N=128,K=256
    int i2 = idx - off;
    frag_jk(i2, 128, &j, &k);
    float v = (k < 128) ? Wt1[(long)j*384 + k] : Wt1[(long)j*384 + 256 + (k-128)];
    g_WCT[i2] = __uint_as_float(f2tf(v));
    return;
  }
  off += 32768;
  if (idx < (off + 24576)){                        // WCI: N=128,K=192
    int i2 = idx - off;
    frag_jk(i2, 128, &j, &k);
    float v = (k < 64) ? Wi1[(long)j*256 + k] : Wi1[(long)j*256 + 128 + (k-64)];
    g_WCI[i2] = __uint_as_float(f2tf(v));
    return;
  }
  off += 24576;
  if (idx < (off + 8192)){                         // WA: N=64,K=128
    int i2 = idx - off;
    frag_jk(i2, 64, &j, &k);
    g_WA[i2] = __uint_as_float(f2tf(Wa1[(long)j*128 + k]));
    return;
  }
  off += 8192;
  if (idx < (off + 8192)){                         // WT16 bf16: N=128,K=128
    int i2 = idx - off;
    frag16_jk(i2, &j, &k);
    g_WT16[i2] = pkbf(Wt1[(long)j*384 + 128 + k], Wt1[(long)j*384 + 128 + k + 1]);
    return;
  }
  off += 8192;
  if (idx < (off + 4096)){                         // WI16 bf16: N=128,K=64
    int i2 = idx - off;
    frag16_jk(i2, &j, &k);
    g_WI16[i2] = pkbf(Wi1[(long)j*256 + 64 + k], Wi1[(long)j*256 + 64 + k + 1]);
    return;
  }
}

// ---- input-gate GEMM (tf32): IG[m][n] = x_m · Wih[n] + bih[n] ----
// grid = (80, 3): blockIdx.y selects the 128-wide gate chunk
__global__ __launch_bounds__(256) void k_ig(
    const float* __restrict__ ide, const float* __restrict__ txe,
    const int* __restrict__ lens, const float* __restrict__ bih)
{
  __shared__ float sB[384];
  const int tid = threadIdx.x, warp = tid>>5, lane = tid&31;
  const int g = lane>>2, tig = lane&3;
  const int ch = blockIdx.y;
  for (int i=tid; i<384; i+=256) sB[i] = bih[i];
  const int r0 = blockIdx.x*128 + warp*16 + g;
  const int r1 = r0 + 8;
  int b0 = r0/5, t0 = r0 - 5*b0;  int p0 = lens[b0] - 5 + t0;
  int b1 = r1/5, t1 = r1 - 5*b1;  int p1 = lens[b1] - 5 + t1;
  const float* id0 = ide + ((long)b0*L_ + p0)*64;
  const float* tx0 = txe + ((long)b0*L_ + p0)*128;
  const float* id1 = ide + ((long)b1*L_ + p1)*64;
  const float* tx1 = txe + ((long)b1*L_ + p1)*128;
  __syncthreads();

  const float4* bp = (const float4*)g_WIHf;
  float acc[16][4];
#pragma unroll
  for (int nt=0;nt<16;nt++){ acc[nt][0]=0.f;acc[nt][1]=0.f;acc[nt][2]=0.f;acc[nt][3]=0.f; }
#pragma unroll
  for (int kt=0;kt<24;kt++){
    int k0 = kt*8 + tig, k4 = k0+4;
    unsigned a0 = f2tf(k0<64 ? id0[k0] : tx0[k0-64]);
    unsigned a2 = f2tf(k4<64 ? id0[k4] : tx0[k4-64]);
    unsigned a1 = f2tf(k0<64 ? id1[k0] : tx1[k0-64]);
    unsigned a3 = f2tf(k4<64 ? id1[k4] : tx1[k4-64]);
#pragma unroll
    for (int n2=0;n2<8;n2++){
      float4 bv = bp[(kt*24 + ch*8 + n2)*32 + lane];
      mma8(acc[2*n2],   a0,a1,a2,a3, __float_as_uint(bv.x), __float_as_uint(bv.y));
      mma8(acc[2*n2+1], a0,a1,a2,a3, __float_as_uint(bv.z), __float_as_uint(bv.w));
    }
  }
#pragma unroll
  for (int nt=0;nt<16;nt++){
    int j = ch*128 + nt*8 + 2*tig;
    float* o0 = g_IG + (long)r0*384 + j;
    float* o1 = g_IG + (long)r1*384 + j;
    o0[0] = acc[nt][0]+sB[j]; o0[1] = acc[nt][1]+sB[j+1];
    o1[0] = acc[nt][2]+sB[j]; o1[1] = acc[nt][3]+sB[j+1];
  }
}

// ---- persistent fused GRU (5 steps) + per-batch prep (ct/ci/alpha) ----
__global__ __launch_bounds__(256) void k_gruall(
    const float* __restrict__ bhh,
    const float* __restrict__ ide, const float* __restrict__ txe,
    const int* __restrict__ lens, const int* __restrict__ sitems,
    const float* __restrict__ bt1, const float* __restrict__ bi1,
    const float* __restrict__ ba1, const float* __restrict__ Wa2,
    const float* __restrict__ ba2)
{
  extern __shared__ float sm[];
  float* sW  = sm;                  // 49152 (W_hh frags; reused after GRU)
  float* sH  = sm + 49152;          // 2048
  float* sB  = sm + 49152+2048;     // 384
  float* sbt = sB + 384;            // 128
  float* sbi = sbt + 128;           // 128
  float* sba = sbi + 128;           // 64
  float* swa2= sba + 64;            // 192
  float* sba2= swa2 + 192;          // 4 (3 used)
  const int tid = threadIdx.x, warp = tid>>5, lane = tid&31;
  const int g = lane>>2, tig = lane&3;
  const int b0 = blockIdx.x*16;

  {
    const float4* gw = (const float4*)g_WHHf;
    float4* swv = (float4*)sW;
    for (int i=tid;i<12288;i+=256) swv[i] = gw[i];
  }
  for (int i=tid;i<384;i+=256) sB[i] = bhh[i];
  if (tid < 128){ sbt[tid] = bt1[tid]; sbi[tid] = bi1[tid]; }
  else if (tid < 192) sba[tid-128] = ba1[tid-128];
  else if (tid < 195) sba2[tid-192] = ba2[tid-192];
  for (int i=tid;i<192;i+=256) swa2[i] = Wa2[i];
  if (tid < 16) g_LI[b0+tid] = sitems[(long)(b0+tid)*L_ + lens[b0+tid]-1];
  __syncthreads();

  // step 0
  for (int i=tid;i<2048;i+=256){
    int bb = i>>7, j = i&127;
    const float* ig = g_IG + ((long)(b0+bb)*5)*384;
    float r = sigf(ig[j]       + sB[j]);
    float z = sigf(ig[128+j]   + sB[128+j]);
    float n = tanhf_fast(ig[256+j] + r*sB[256+j]);
    sH[i] = (1.f - z)*n;
  }
  __syncthreads();

  const float4* swv4 = (const float4*)sW;
  for (int t=1;t<5;t++){
    float acc[3][2][4];
#pragma unroll
    for (int gate=0;gate<3;gate++)
#pragma unroll
      for (int s=0;s<2;s++){ acc[gate][s][0]=0.f;acc[gate][s][1]=0.f;acc[gate][s][2]=0.f;acc[gate][s][3]=0.f; }
#pragma unroll
    for (int kt=0;kt<16;kt++){
      int k0 = kt*8 + tig;
      unsigned a0 = f2tf(sH[g*128     + k0]);
      unsigned a1 = f2tf(sH[(g+8)*128 + k0]);
      unsigned a2 = f2tf(sH[g*128     + k0+4]);
      unsigned a3 = f2tf(sH[(g+8)*128 + k0+4]);
#pragma unroll
      for (int gate=0;gate<3;gate++){
        int pr = gate*8 + warp;
        float4 bv = swv4[(kt*24 + pr)*32 + lane];
        mma8(acc[gate][0], a0,a1,a2,a3, __float_as_uint(bv.x), __float_as_uint(bv.y));
        mma8(acc[gate][1], a0,a1,a2,a3, __float_as_uint(bv.z), __float_as_uint(bv.w));
      }
    }
    __syncthreads();
    const float* ig0 = g_IG + (((long)(b0+g))*5   + t)*384;
    const float* ig1 = g_IG + (((long)(b0+g+8))*5 + t)*384;
#pragma unroll
    for (int s=0;s<2;s++){
#pragma unroll
      for (int cc=0;cc<2;cc++){
        int j = warp*16 + s*8 + tig*2 + cc;
        {
          float r = sigf(ig0[j]       + acc[0][s][cc] + sB[j]);
          float z = sigf(ig0[128+j]   + acc[1][s][cc] + sB[128+j]);
          float n = tanhf_fast(ig0[256+j] + r*(acc[2][s][cc] + sB[256+j]));
          float hp = sH[g*128 + j];
          sH[g*128 + j] = (1.f-z)*n + z*hp;
        }
        {
          float r = sigf(ig1[j]       + acc[0][s][cc+2] + sB[j]);
          float z = sigf(ig1[128+j]   + acc[1][s][cc+2] + sB[128+j]);
          float n = tanhf_fast(ig1[256+j] + r*(acc[2][s][cc+2] + sB[256+j]));
          float hp = sH[(g+8)*128 + j];
          sH[(g+8)*128 + j] = (1.f-z)*n + z*hp;
        }
      }
    }
    __syncthreads();
  }

  // ================= fused per-batch prep =================
  const int L0 = lens[b0+g], L1 = lens[b0+8+g];
  const float* lt0 = txe + ((long)(b0+g)*L_   + L0-1)*128;
  const float* lt1 = txe + ((long)(b0+8+g)*L_ + L1-1)*128;
  const float* li0 = ide + ((long)(b0+g)*L_   + L0-1)*64;
  const float* li1 = ide + ((long)(b0+8+g)*L_ + L1-1)*64;
  const float* h0  = sH + g*128;
  const float* h1  = sH + (g+8)*128;

  // CT: M=16, N=128 (warp w owns n2=w), K=256 = [lt | h]
  {
    float acc[2][4];
    acc[0][0]=0.f;acc[0][1]=0.f;acc[0][2]=0.f;acc[0][3]=0.f;
    acc[1][0]=0.f;acc[1][1]=0.f;acc[1][2]=0.f;acc[1][3]=0.f;
    const float4* bp = (const float4*)g_WCT;
#pragma unroll
    for (int kt=0;kt<32;kt++){
      int k0 = kt*8 + tig, k4 = k0+4;
      unsigned a0 = f2tf(k0<128 ? lt0[k0] : h0[k0-128]);
      unsigned a2 = f2tf(k4<128 ? lt0[k4] : h0[k4-128]);
      unsigned a1 = f2tf(k0<128 ? lt1[k0] : h1[k0-128]);
      unsigned a3 = f2tf(k4<128 ? lt1[k4] : h1[k4-128]);
      float4 bv = bp[(kt*8 + warp)*32 + lane];
      mma8(acc[0], a0,a1,a2,a3, __float_as_uint(bv.x), __float_as_uint(bv.y));
      mma8(acc[1], a0,a1,a2,a3, __float_as_uint(bv.z), __float_as_uint(bv.w));
    }
#pragma unroll
    for (int s=0;s<2;s++){
      int j = (2*warp+s)*8 + 2*tig;
      float* o0 = g_CT + (long)(b0+g)*128 + j;
      float* o1 = g_CT + (long)(b0+8+g)*128 + j;
      o0[0] = acc[s][0]+sbt[j]; o0[1] = acc[s][1]+sbt[j+1];
      o1[0] = acc[s][2]+sbt[j]; o1[1] = acc[s][3]+sbt[j+1];
    }
  }
  // CI: K=192 = [lid | h]
  {
    float acc[2][4];
    acc[0][0]=0.f;acc[0][1]=0.f;acc[0][2]=0.f;acc[0][3]=0.f;
    acc[1][0]=0.f;acc[1][1]=0.f;acc[1][2]=0.f;acc[1][3]=0.f;
    const float4* bp = (const float4*)g_WCI;
#pragma unroll
    for (int kt=0;kt<24;kt++){
      int k0 = kt*8 + tig, k4 = k0+4;
      unsigned a0 = f2tf(k0<64 ? li0[k0] : h0[k0-64]);
      unsigned a2 = f2tf(k4<64 ? li0[k4] : h0[k4-64]);
      unsigned a1 = f2tf(k0<64 ? li1[k0] : h1[k0-64]);
      unsigned a3 = f2tf(k4<64 ? li1[k4] : h1[k4-64]);
      float4 bv = bp[(kt*8 + warp)*32 + lane];
      mma8(acc[0], a0,a1,a2,a3, __float_as_uint(bv.x), __float_as_uint(bv.y));
      mma8(acc[1], a0,a1,a2,a3, __float_as_uint(bv.z), __float_as_uint(bv.w));
    }
#pragma unroll
    for (int s=0;s<2;s++){
      int j = (2*warp+s)*8 + 2*tig;
      float* o0 = g_CI + (long)(b0+g)*128 + j;
      float* o1 = g_CI + (long)(b0+8+g)*128 + j;
      o0[0] = acc[s][0]+sbi[j]; o0[1] = acc[s][1]+sbi[j+1];
      o1[0] = acc[s][2]+sbi[j]; o1[1] = acc[s][3]+sbi[j+1];
    }
  }
  // alpha: N=64 (warps 0-3, n2=warp), K=128 = h ; a1s reuses sW space
  float (*a1s)[64] = (float(*)[64])sW;
  float (*lg)[3]   = (float(*)[3])(sW + 16*64);
  {
    if (warp < 4){
      float acc[2][4];
      acc[0][0]=0.f;acc[0][1]=0.f;acc[0][2]=0.f;acc[0][3]=0.f;
      acc[1][0]=0.f;acc[1][1]=0.f;acc[1][2]=0.f;acc[1][3]=0.f;
      const float4* bp = (const float4*)g_WA;
#pragma unroll
      for (int kt=0;kt<16;kt++){
        int k0 = kt*8 + tig;
        unsigned a0 = f2tf(h0[k0]), a2 = f2tf(h0[k0+4]);
        unsigned a1 = f2tf(h1[k0]), a3 = f2tf(h1[k0+4]);
        float4 bv = bp[(kt*4 + warp)*32 + lane];
        mma8(acc[0], a0,a1,a2,a3, __float_as_uint(bv.x), __float_as_uint(bv.y));
        mma8(acc[1], a0,a1,a2,a3, __float_as_uint(bv.z), __float_as_uint(bv.w));
      }
#pragma unroll
      for (int s=0;s<2;s++){
        int u = (2*warp+s)*8 + 2*tig;
        a1s[g][u]     = fmaxf(acc[s][0]+sba[u],0.f);
        a1s[g][u+1]   = fmaxf(acc[s][1]+sba[u+1],0.f);
        a1s[g+8][u]   = fmaxf(acc[s][2]+sba[u],0.f);
        a1s[g+8][u+1] = fmaxf(acc[s][3]+sba[u+1],0.f);
      }
    }
    __syncthreads();
    if (tid < 48){
      int bb = tid/3, gg = tid%3;
      float s = sba2[gg];
      const float* w = swa2 + gg*64;
      for (int u=0;u<64;u++) s += w[u]*a1s[bb][u];
      lg[bb][gg] = s;
    }
    __syncthreads();
    if (tid < 16){
      float l0=lg[tid][0], l1=lg[tid][1], l2=lg[tid][2];
      float m = fmaxf(l0, fmaxf(l1,l2));
      float e0=__expf(l0-m), e1=__expf(l1-m), e2=__expf(l2-m);
      float inv = 1.f/(e0+e1+e2);
      g_AL[(b0+tid)*3+0]=e0*inv; g_AL[(b0+tid)*3+1]=e1*inv; g_AL[(b0+tid)*3+2]=e2*inv;
    }
  }
}

// ---- fused scorer: 2 batches/block, text-pass A staged in smem ----
__global__ __launch_bounds__(256, 3) void k_score(
    const float* __restrict__ ctxe, const float* __restrict__ cide,
    const int* __restrict__ cids, const float* __restrict__ co,
    const float* __restrict__ Wt2, const float* __restrict__ bt2,
    const float* __restrict__ Wi2, const float* __restrict__ bi2,
    const float* __restrict__ betac, const float* __restrict__ lTc,
    const float* __restrict__ lTt, const float* __restrict__ lTi,
    float* __restrict__ out)
{
  extern __shared__ unsigned sAx[];   // 16384 u32 = 64KB: text A frags, 2 batches
  __shared__ float ctv[2][128], civ[2][128], w2t[128], w2i[128];
  __shared__ float sco[2][3][128];
  __shared__ float mx3[2][3], inv3[2][3], sS[2];
  __shared__ float mixv[2][128];
  const int bA = 2*blockIdx.x, bB = bA + 1;
  const int tid = threadIdx.x;
  const int warp = tid>>5, lane = tid&31;
  const int g = lane>>2, tig = lane&3;
  const int r0 = warp*16 + g, r1 = r0 + 8;

  // ---- stage text A (both batches) into smem, fragment-ordered bf16 ----
  {
    const float* E[2] = { ctxe + (long)bA*C_*128, ctxe + (long)bB*C_*128 };
    for (int u = tid; u < 8192; u += 256){
      int q = u >> 12, rem = u & 4095;
      int row = rem >> 5, kseg = rem & 31;
      int k0 = kseg*4;
      unsigned u0 = 0u, u1 = 0u;
      if (row < C_){
        float4 v = *(const float4*)(E[q] + (long)row*128 + k0);
        u0 = pkbf(v.x, v.y); u1 = pkbf(v.z, v.w);
      }
      int kt = kseg >> 2;
      int kk0 = (kseg & 3)*4;
      int hi = (kk0 >= 8) ? 2 : 0;
      int tb = (kk0 & 7) >> 1;              // 0 or 2
      int comp = hi + (((row & 15) < 8) ? 0 : 1);
      int w = row >> 4, gg = row & 7;
      int base = (((q*8 + kt)*8 + w)*32);
      sAx[(base + gg*4 + tb)*4 + comp]     = u0;
      sAx[(base + gg*4 + tb + 1)*4 + comp] = u1;
    }
  }
  if (tid < 128){
    ctv[0][tid]=g_CT[bA*128+tid]; civ[0][tid]=g_CI[bA*128+tid];
    w2t[tid]=Wt2[tid];            w2i[tid]=Wi2[tid];
  } else {
    int t = tid-128;
    ctv[1][t]=g_CT[bB*128+t];     civ[1][t]=g_CI[bB*128+t];
  }
  const float bc = betac[0], eTc = expf(lTc[0]);
  if (tid < 100){
    long li = g_LI[bA];
    sco[0][0][tid] = co[li*V_ + cids[(long)bA*C_+tid]] * bc / eTc;
  } else if (tid >= 128 && tid < 228){
    int t = tid-128;
    long li = g_LI[bB];
    sco[1][0][t] = co[li*V_ + cids[(long)bB*C_+t]] * bc / eTc;
  }
  const float Tt = expf(lTt[0]), Ti = expf(lTi[0]);
  __syncthreads();

  // ---- text pass: K=128; A from smem, n2 outer, B shared across batches ----
  {
    const uint4* aA4 = (const uint4*)sAx + (0*8)*8*32;
    const uint4* aB4 = (const uint4*)sAx + (1*8)*8*32;
    const uint4* bp = (const uint4*)g_WT16;
    float pA0=0.f, pA1=0.f, pB0=0.f, pB1=0.f;
#pragma unroll
    for (int n2=0;n2<8;n2++){
      float cA0[4]={0.f,0.f,0.f,0.f}, cA1[4]={0.f,0.f,0.f,0.f};
      float cB0[4]={0.f,0.f,0.f,0.f}, cB1[4]={0.f,0.f,0.f,0.f};
#pragma unroll
      for (int kt=0;kt<8;kt++){
        uint4 av = aA4[(kt*8 + warp)*32 + lane];
        uint4 bw = aB4[(kt*8 + warp)*32 + lane];
        uint4 bv = bp[(kt*8 + n2)*32 + lane];
        mma16(cA0, av.x,av.y,av.z,av.w, bv.x, bv.y);
        mma16(cA1, av.x,av.y,av.z,av.w, bv.z, bv.w);
        mma16(cB0, bw.x,bw.y,bw.z,bw.w, bv.x, bv.y);
        mma16(cB1, bw.x,bw.y,bw.z,bw.w, bv.z, bv.w);
      }
      {
        int j0 = (2*n2)*8 + 2*tig;
        float w0=w2t[j0], w1=w2t[j0+1];
        float c0=ctv[0][j0], c1=ctv[0][j0+1];
        pA0 += w0*fmaxf(c0+cA0[0],0.f) + w1*fmaxf(c1+cA0[1],0.f);
        pA1 += w0*fmaxf(c0+cA0[2],0.f) + w1*fmaxf(c1+cA0[3],0.f);
        c0=ctv[1][j0]; c1=ctv[1][j0+1];
        pB0 += w0*fmaxf(c0+cB0[0],0.f) + w1*fmaxf(c1+cB0[1],0.f);
        pB1 += w0*fmaxf(c0+cB0[2],0.f) + w1*fmaxf(c1+cB0[3],0.f);
      }
      {
        int j0 = (2*n2+1)*8 + 2*tig;
        float w0=w2t[j0], w1=w2t[j0+1];
        float c0=ctv[0][j0], c1=ctv[0][j0+1];
        pA0 += w0*fmaxf(c0+cA1[0],0.f) + w1*fmaxf(c1+cA1[1],0.f);
        pA1 += w0*fmaxf(c0+cA1[2],0.f) + w1*fmaxf(c1+cA1[3],0.f);
        c0=ctv[1][j0]; c1=ctv[1][j0+1];
        pB0 += w0*fmaxf(c0+cB1[0],0.f) + w1*fmaxf(c1+cB1[1],0.f);
        pB1 += w0*fmaxf(c0+cB1[2],0.f) + w1*fmaxf(c1+cB1[3],0.f);
      }
    }
    pA0 += __shfl_xor_sync(0xffffffffu,pA0,1); pA0 += __shfl_xor_sync(0xffffffffu,pA0,2);
    pA1 += __shfl_xor_sync(0xffffffffu,pA1,1); pA1 += __shfl_xor_sync(0xffffffffu,pA1,2);
    pB0 += __shfl_xor_sync(0xffffffffu,pB0,1); pB0 += __shfl_xor_sync(0xffffffffu,pB0,2);
    pB1 += __shfl_xor_sync(0xffffffffu,pB1,1); pB1 += __shfl_xor_sync(0xffffffffu,pB1,2);
    if (tig==0){
      if (r0 < C_){ sco[0][1][r0] = (pA0 + bt2[0]) / Tt; sco[1][1][r0] = (pB0 + bt2[0]) / Tt; }
      if (r1 < C_){ sco[0][1][r1] = (pA1 + bt2[0]) / Tt; sco[1][1][r1] = (pB1 + bt2[0]) / Tt; }
    }
  }
  // ---- id pass: K=64 (register-prefetched, as R13) ----
  {
    const float* E0 = cide + (long)bA*C_*64;
    const float* E1 = cide + (long)bB*C_*64;
    unsigned aA[4][4], aB[4][4];
#pragma unroll
    for (int kt=0;kt<4;kt++){
      const int k0 = kt*16 + tig*2;
      aA[kt][0]=0u; aA[kt][1]=0u; aA[kt][2]=0u; aA[kt][3]=0u;
      aB[kt][0]=0u; aB[kt][1]=0u; aB[kt][2]=0u; aB[kt][3]=0u;
      if (r0 < C_){
        float2 x = *(const float2*)(E0 + (long)r0*64 + k0);
        float2 y = *(const float2*)(E0 + (long)r0*64 + k0 + 8);
        aA[kt][0] = pkbf(x.x,x.y); aA[kt][2] = pkbf(y.x,y.y);
        x = *(const float2*)(E1 + (long)r0*64 + k0);
        y = *(const float2*)(E1 + (long)r0*64 + k0 + 8);
        aB[kt][0] = pkbf(x.x,x.y); aB[kt][2] = pkbf(y.x,y.y);
      }
      if (r1 < C_){
        float2 x = *(const float2*)(E0 + (long)r1*64 + k0);
        float2 y = *(const float2*)(E0 + (long)r1*64 + k0 + 8);
        aA[kt][1] = pkbf(x.x,x.y); aA[kt][3] = pkbf(y.x,y.y);
        x = *(const float2*)(E1 + (long)r1*64 + k0);
        y = *(const float2*)(E1 + (long)r1*64 + k0 + 8);
        aB[kt][1] = pkbf(x.x,x.y); aB[kt][3] = pkbf(y.x,y.y);
      }
    }
    const uint4* bp = (const uint4*)g_WI16;
    float pA0=0.f, pA1=0.f, pB0=0.f, pB1=0.f;
#pragma unroll
    for (int n2=0;n2<8;n2++){
      float cA0[4]={0.f,0.f,0.f,0.f}, cA1[4]={0.f,0.f,0.f,0.f};
      float cB0[4]={0.f,0.f,0.f,0.f}, cB1[4]={0.f,0.f,0.f,0.f};
#pragma unroll
      for (int kt=0;kt<4;kt++){
        uint4 bv = bp[(kt*8 + n2)*32 + lane];
        mma16(cA0, aA[kt][0],aA[kt][1],aA[kt][2],aA[kt][3], bv.x, bv.y);
        mma16(cA1, aA[kt][0],aA[kt][1],aA[kt][2],aA[kt][3], bv.z, bv.w);
        mma16(cB0, aB[kt][0],aB[kt][1],aB[kt][2],aB[kt][3], bv.x, bv.y);
        mma16(cB1, aB[kt][0],aB[kt][1],aB[kt][2],aB[kt][3], bv.z, bv.w);
      }
      {
        int j0 = (2*n2)*8 + 2*tig;
        float w0=w2i[j0], w1=w2i[j0+1];
        float c0=civ[0][j0], c1=civ[0][j0+1];
        pA0 += w0*fmaxf(c0+cA0[0],0.f) + w1*fmaxf(c1+cA0[1],0.f);
        pA1 += w0*fmaxf(c0+cA0[2],0.f) + w1*fmaxf(c1+cA0[3],0.f);
        c0=civ[1][j0]; c1=civ[1][j0+1];
        pB0 += w0*fmaxf(c0+cB0[0],0.f) + w1*fmaxf(c1+cB0[1],0.f);
        pB1 += w0*fmaxf(c0+cB0[2],0.f) + w1*fmaxf(c1+cB0[3],0.f);
      }
      {
        int j0 = (2*n2+1)*8 + 2*tig;
        float w0=w2i[j0], w1=w2i[j0+1];
        float c0=civ[0][j0], c1=civ[0][j0+1];
        pA0 += w0*fmaxf(c0+cA1[0],0.f) + w1*fmaxf(c1+cA1[1],0.f);
        pA1 += w0*fmaxf(c0+cA1[2],0.f) + w1*fmaxf(c1+cA1[3],0.f);
        c0=civ[1][j0]; c1=civ[1][j0+1];
        pB0 += w0*fmaxf(c0+cB1[0],0.f) + w1*fmaxf(c1+cB1[1],0.f);
        pB1 += w0*fmaxf(c0+cB1[2],0.f) + w1*fmaxf(c1+cB1[3],0.f);
      }
    }
    pA0 += __shfl_xor_sync(0xffffffffu,pA0,1); pA0 += __shfl_xor_sync(0xffffffffu,pA0,2);
    pA1 += __shfl_xor_sync(0xffffffffu,pA1,1); pA1 += __shfl_xor_sync(0xffffffffu,pA1,2);
    pB0 += __shfl_xor_sync(0xffffffffu,pB0,1); pB0 += __shfl_xor_sync(0xffffffffu,pB0,2);
    pB1 += __shfl_xor_sync(0xffffffffu,pB1,1); pB1 += __shfl_xor_sync(0xffffffffu,pB1,2);
    if (tig==0){
      if (r0 < C_){ sco[0][2][r0] = (pA0 + bi2[0]) / Ti; sco[1][2][r0] = (pB0 + bi2[0]) / Ti; }
      if (r1 < C_){ sco[0][2][r1] = (pA1 + bi2[0]) / Ti; sco[1][2][r1] = (pB1 + bi2[0]) / Ti; }
    }
  }
  __syncthreads();

  // 6 softmaxes: warp w<6 handles (batch = w/3, channel = w%3)
  if (warp < 6){
    int bs = warp/3, chn = warp%3;
    float m = -1e30f;
    for (int q=lane;q<C_;q+=32) m = fmaxf(m, sco[bs][chn][q]);
    m = wmax(m);
    float s = 0.f;
    for (int q=lane;q<C_;q+=32) s += __expf(sco[bs][chn][q]-m);
    s = wsum(s);
    if (lane==0){ mx3[bs][chn]=m; inv3[bs][chn]=1.f/s; }
  }
  __syncthreads();
  if (tid < 100){
    const float a0=g_AL[bA*3], a1=g_AL[bA*3+1], a2=g_AL[bA*3+2];
    mixv[0][tid] = 0.01f
      + a0*__expf(sco[0][0][tid]-mx3[0][0])*inv3[0][0]
      + a1*__expf(sco[0][1][tid]-mx3[0][1])*inv3[0][1]
      + a2*__expf(sco[0][2][tid]-mx3[0][2])*inv3[0][2];
  } else if (tid >= 128 && tid < 228){
    int t = tid-128;
    const float a0=g_AL[bB*3], a1=g_AL[bB*3+1], a2=g_AL[bB*3+2];
    mixv[1][t] = 0.01f
      + a0*__expf(sco[1][0][t]-mx3[1][0])*inv3[1][0]
      + a1*__expf(sco[1][1][t]-mx3[1][1])*inv3[1][1]
      + a2*__expf(sco[1][2][t]-mx3[1][2])*inv3[1][2];
  }
  __syncthreads();
  if (warp < 2){
    float s = 0.f;
    for (int q=lane;q<C_;q+=32) s += mixv[warp][q];
    s = wsum(s);
    if (lane==0) sS[warp] = 1.f/s;
  }
  __syncthreads();
  if (tid < 100) out[(long)bA*C_ + tid] = mixv[0][tid]*sS[0];
  else if (tid >= 128 && tid < 228) out[(long)bB*C_ + (tid-128)] = mixv[1][tid-128]*sS[1];
}

extern "C" void kernel_launch(void* const* d_in, const int* in_sizes, int n_in,
                              void* d_out, int out_size) {
  const int*   sitems = (const int*)  d_in[0];
  const float* ide    = (const float*)d_in[1];
  const float* txe    = (const float*)d_in[2];
  const int*   lens   = (const int*)  d_in[3];
  const int*   cids   = (const int*)  d_in[4];
  const float* cide   = (const float*)d_in[5];
  const float* ctxe   = (const float*)d_in[6];
  const float* co     = (const float*)d_in[7];
  const float* Wih    = (const float*)d_in[8];
  const float* Whh    = (const float*)d_in[9];
  const float* bih    = (const float*)d_in[10];
  const float* bhh    = (const float*)d_in[11];
  const float* Wt1    = (const float*)d_in[12];
  const float* bt1    = (const float*)d_in[13];
  const float* Wt2    = (const float*)d_in[14];
  const float* bt2    = (const float*)d_in[15];
  const float* Wi1    = (const float*)d_in[16];
  const float* bi1    = (const float*)d_in[17];
  const float* Wi2    = (const float*)d_in[18];
  const float* bi2    = (const float*)d_in[19];
  const float* Wa1    = (const float*)d_in[20];
  const float* ba1    = (const float*)d_in[21];
  const float* Wa2    = (const float*)d_in[22];
  const float* ba2    = (const float*)d_in[23];
  // d_in[24] = Wstab: unused (P_stable is uniform = 1/C exactly)
  const float* betac  = (const float*)d_in[25];
  const float* lTc    = (const float*)d_in[26];
  const float* lTt    = (const float*)d_in[27];
  const float* lTi    = (const float*)d_in[28];
  float* out = (float*)d_out;

  const int GRU_SMEM = (49152 + 2048 + 384 + 128 + 128 + 64 + 192 + 4) * 4;
  cudaFuncSetAttribute(k_gruall, cudaFuncAttributeMaxDynamicSharedMemorySize, GRU_SMEM);
  const int SCORE_SMEM = 16384 * 4;  // 64KB text-A staging
  cudaFuncSetAttribute(k_score, cudaFuncAttributeMaxDynamicSharedMemorySize, SCORE_SMEM);

  const int WPREP_N = 73728+49152+32768+24576+8192+8192+4096;
  k_wprep<<<(WPREP_N+255)/256, 256>>>(Wih, Whh, Wt1, Wi1, Wa1);
  k_ig<<<dim3(80,3), 256>>>(ide, txe, lens, bih);
  k_gruall<<<128, 256, GRU_SMEM>>>(bhh, ide, txe, lens, sitems,
                                   bt1, bi1, ba1, Wa2, ba2);
  k_score<<<B_/2, 256, SCORE_SMEM>>>(ctxe, cide, cids, co, Wt2, bt2, Wi2, bi2,
                                     betac, lTc, lTt, lTi, out);
}

// round 16
// speedup vs baseline: 1.0720x; 1.0720x over previous
#include <cuda_runtime.h>
#include <cuda_bf16.h>
#include <math.h>

#define B_  2048
#define L_  200
#define C_  100
#define V_  2000

// ---------------- scratch ----------------
__device__ float g_IG  [B_*5*384];
__device__ float g_CT  [B_*128];
__device__ float g_CI  [B_*128];
__device__ float g_AL  [B_*3];
__device__ float g_WIHf[73728];        // W_ih (N=384,K=192) tf32 frag order
__device__ float g_WHHf[49152];        // W_hh (N=384,K=128) tf32 frag order
__device__ float g_WCT [32768];        // [Wt1 src | Wt1 h]  (N=128,K=256) tf32 frag
__device__ float g_WCI [24576];        // [Wi1 src | Wi1 h]  (N=128,K=192) tf32 frag
__device__ float g_WA  [8192];         // Wa1 (N=64,K=128) tf32 frag
__device__ unsigned g_WT16[8192];      // Wt1 mid slab bf16 m16n8k16 frag (32KB)
__device__ unsigned g_WI16[4096];      // Wi1 mid slab bf16 m16n8k16 frag (16KB)
__device__ int   g_LI  [B_];

__device__ __forceinline__ float sigf(float x){ return 1.0f/(1.0f+__expf(-x)); }
__device__ __forceinline__ float tanhf_fast(float x){
  x = fminf(fmaxf(x,-15.f),15.f);
  float e = __expf(2.f*x);
  return (e-1.f)/(e+1.f);
}
__device__ __forceinline__ float wsum(float v){
#pragma unroll
  for (int o=16;o;o>>=1) v += __shfl_xor_sync(0xffffffffu, v, o);
  return v;
}
__device__ __forceinline__ float wmax(float v){
#pragma unroll
  for (int o=16;o;o>>=1) v = fmaxf(v, __shfl_xor_sync(0xffffffffu, v, o));
  return v;
}
__device__ __forceinline__ unsigned f2tf(float x){
  unsigned r; asm("cvt.rna.tf32.f32 %0, %1;" : "=r"(r) : "f"(x)); return r;
}
__device__ __forceinline__ unsigned pkbf(float lo, float hi){
  __nv_bfloat162 h = __floats2bfloat162_rn(lo, hi);
  return *(unsigned*)&h;
}
__device__ __forceinline__ void mma8(float* d,
    unsigned a0, unsigned a1, unsigned a2, unsigned a3,
    unsigned b0, unsigned b1){
  asm volatile(
    "mma.sync.aligned.m16n8k8.row.col.f32.tf32.tf32.f32 "
    "{%0,%1,%2,%3},{%4,%5,%6,%7},{%8,%9},{%0,%1,%2,%3};\n"
    : "+f"(d[0]),"+f"(d[1]),"+f"(d[2]),"+f"(d[3])
    : "r"(a0),"r"(a1),"r"(a2),"r"(a3),"r"(b0),"r"(b1));
}
__device__ __forceinline__ void mma16(float* d,
    unsigned a0, unsigned a1, unsigned a2, unsigned a3,
    unsigned b0, unsigned b1){
  asm volatile(
    "mma.sync.aligned.m16n8k16.row.col.f32.bf16.bf16.f32 "
    "{%0,%1,%2,%3},{%4,%5,%6,%7},{%8,%9},{%0,%1,%2,%3};\n"
    : "+f"(d[0]),"+f"(d[1]),"+f"(d[2]),"+f"(d[3])
    : "r"(a0),"r"(a1),"r"(a2),"r"(a3),"r"(b0),"r"(b1));
}

// decode tf32 fragment-order flat index -> (j,k) for weight W[N][K]
__device__ __forceinline__ void frag_jk(int idx, int N, int* jj, int* kk){
  int c = idx & 3, lane = (idx>>2)&31;
  int P = N >> 4;
  int pr = (idx>>7) % P;
  int kt = idx / (128*P);
  int nt = 2*pr + (c>>1), p = c&1;
  *jj = nt*8 + (lane>>2);
  *kk = kt*8 + (lane&3) + 4*p;
}
// decode bf16 m16n8k16 frag (uint4-of-n-pairs) flat uint index -> (j, k0)
__device__ __forceinline__ void frag16_jk(int idx, int* jj, int* kk){
  int w = idx & 3, lane = (idx>>2)&31, n2 = (idx>>7)&7, kt = idx>>10;
  int n = 2*n2 + (w>>1);
  *jj = n*8 + (lane>>2);
  *kk = kt*16 + (lane&3)*2 + (w&1)*8;
}

// ---- prepare all fragment-ordered weights ----
__global__ void k_wprep(const float* __restrict__ Wih, const float* __restrict__ Whh,
                        const float* __restrict__ Wt1, const float* __restrict__ Wi1,
                        const float* __restrict__ Wa1){
  int idx = blockIdx.x*blockDim.x + threadIdx.x;
  int j, k;
  int off = 0;
  if (idx < (off += 73728)){                       // Wih: N=384,K=192
    frag_jk(idx, 384, &j, &k);
    g_WIHf[idx] = __uint_as_float(f2tf(Wih[(long)j*192 + k]));
    return;
  }
  if (idx < (off + 49152)){                        // Whh: N=384,K=128
    int i2 = idx - off;
    frag_jk(i2, 384, &j, &k);
    g_WHHf[i2] = __uint_as_float(f2tf(Whh[(long)j*128 + k]));
    return;
  }
  off += 49152;
  if (idx < (off + 32768)){                        // WCT: N=128,K=256
    int i2 = idx - off;
    frag_jk(i2, 128, &j, &k);
    float v = (k < 128) ? Wt1[(long)j*384 + k] : Wt1[(long)j*384 + 256 + (k-128)];
    g_WCT[i2] = __uint_as_float(f2tf(v));
    return;
  }
  off += 32768;
  if (idx < (off + 24576)){                        // WCI: N=128,K=192
    int i2 = idx - off;
    frag_jk(i2, 128, &j, &k);
    float v = (k < 64) ? Wi1[(long)j*256 + k] : Wi1[(long)j*256 + 128 + (k-64)];
    g_WCI[i2] = __uint_as_float(f2tf(v));
    return;
  }
  off += 24576;
  if (idx < (off + 8192)){                         // WA: N=64,K=128
    int i2 = idx - off;
    frag_jk(i2, 64, &j, &k);
    g_WA[i2] = __uint_as_float(f2tf(Wa1[(long)j*128 + k]));
    return;
  }
  off += 8192;
  if (idx < (off + 8192)){                         // WT16 bf16: N=128,K=128
    int i2 = idx - off;
    frag16_jk(i2, &j, &k);
    g_WT16[i2] = pkbf(Wt1[(long)j*384 + 128 + k], Wt1[(long)j*384 + 128 + k + 1]);
    return;
  }
  off += 8192;
  if (idx < (off + 4096)){                         // WI16 bf16: N=128,K=64
    int i2 = idx - off;
    frag16_jk(i2, &j, &k);
    g_WI16[i2] = pkbf(Wi1[(long)j*256 + 64 + k], Wi1[(long)j*256 + 64 + k + 1]);
    return;
  }
}

// ---- input-gate GEMM (tf32): IG[m][n] = x_m · Wih[n] + bih[n] ----
// grid = (80, 3): blockIdx.y selects the 128-wide gate chunk
__global__ __launch_bounds__(256) void k_ig(
    const float* __restrict__ ide, const float* __restrict__ txe,
    const int* __restrict__ lens, const float* __restrict__ bih)
{
  __shared__ float sB[384];
  const int tid = threadIdx.x, warp = tid>>5, lane = tid&31;
  const int g = lane>>2, tig = lane&3;
  const int ch = blockIdx.y;
  for (int i=tid; i<384; i+=256) sB[i] = bih[i];
  const int r0 = blockIdx.x*128 + warp*16 + g;
  const int r1 = r0 + 8;
  int b0 = r0/5, t0 = r0 - 5*b0;  int p0 = lens[b0] - 5 + t0;
  int b1 = r1/5, t1 = r1 - 5*b1;  int p1 = lens[b1] - 5 + t1;
  const float* id0 = ide + ((long)b0*L_ + p0)*64;
  const float* tx0 = txe + ((long)b0*L_ + p0)*128;
  const float* id1 = ide + ((long)b1*L_ + p1)*64;
  const float* tx1 = txe + ((long)b1*L_ + p1)*128;
  __syncthreads();

  const float4* bp = (const float4*)g_WIHf;
  float acc[16][4];
#pragma unroll
  for (int nt=0;nt<16;nt++){ acc[nt][0]=0.f;acc[nt][1]=0.f;acc[nt][2]=0.f;acc[nt][3]=0.f; }
#pragma unroll
  for (int kt=0;kt<24;kt++){
    int k0 = kt*8 + tig, k4 = k0+4;
    unsigned a0 = f2tf(k0<64 ? id0[k0] : tx0[k0-64]);
    unsigned a2 = f2tf(k4<64 ? id0[k4] : tx0[k4-64]);
    unsigned a1 = f2tf(k0<64 ? id1[k0] : tx1[k0-64]);
    unsigned a3 = f2tf(k4<64 ? id1[k4] : tx1[k4-64]);
#pragma unroll
    for (int n2=0;n2<8;n2++){
      float4 bv = bp[(kt*24 + ch*8 + n2)*32 + lane];
      mma8(acc[2*n2],   a0,a1,a2,a3, __float_as_uint(bv.x), __float_as_uint(bv.y));
      mma8(acc[2*n2+1], a0,a1,a2,a3, __float_as_uint(bv.z), __float_as_uint(bv.w));
    }
  }
#pragma unroll
  for (int nt=0;nt<16;nt++){
    int j = ch*128 + nt*8 + 2*tig;
    float* o0 = g_IG + (long)r0*384 + j;
    float* o1 = g_IG + (long)r1*384 + j;
    o0[0] = acc[nt][0]+sB[j]; o0[1] = acc[nt][1]+sB[j+1];
    o1[0] = acc[nt][2]+sB[j]; o1[1] = acc[nt][3]+sB[j+1];
  }
}

// ---- persistent fused GRU (5 steps) + per-batch prep (ct/ci/alpha) ----
__global__ __launch_bounds__(256) void k_gruall(
    const float* __restrict__ bhh,
    const float* __restrict__ ide, const float* __restrict__ txe,
    const int* __restrict__ lens, const int* __restrict__ sitems,
    const float* __restrict__ bt1, const float* __restrict__ bi1,
    const float* __restrict__ ba1, const float* __restrict__ Wa2,
    const float* __restrict__ ba2)
{
  extern __shared__ float sm[];
  float* sW  = sm;                  // 49152 (W_hh frags; reused after GRU)
  float* sH  = sm + 49152;          // 2048
  float* sB  = sm + 49152+2048;     // 384
  float* sbt = sB + 384;            // 128
  float* sbi = sbt + 128;           // 128
  float* sba = sbi + 128;           // 64
  float* swa2= sba + 64;            // 192
  float* sba2= swa2 + 192;          // 4 (3 used)
  const int tid = threadIdx.x, warp = tid>>5, lane = tid&31;
  const int g = lane>>2, tig = lane&3;
  const int b0 = blockIdx.x*16;

  {
    const float4* gw = (const float4*)g_WHHf;
    float4* swv = (float4*)sW;
    for (int i=tid;i<12288;i+=256) swv[i] = gw[i];
  }
  for (int i=tid;i<384;i+=256) sB[i] = bhh[i];
  if (tid < 128){ sbt[tid] = bt1[tid]; sbi[tid] = bi1[tid]; }
  else if (tid < 192) sba[tid-128] = ba1[tid-128];
  else if (tid < 195) sba2[tid-192] = ba2[tid-192];
  for (int i=tid;i<192;i+=256) swa2[i] = Wa2[i];
  if (tid < 16) g_LI[b0+tid] = sitems[(long)(b0+tid)*L_ + lens[b0+tid]-1];
  __syncthreads();

  // step 0
  for (int i=tid;i<2048;i+=256){
    int bb = i>>7, j = i&127;
    const float* ig = g_IG + ((long)(b0+bb)*5)*384;
    float r = sigf(ig[j]       + sB[j]);
    float z = sigf(ig[128+j]   + sB[128+j]);
    float n = tanhf_fast(ig[256+j] + r*sB[256+j]);
    sH[i] = (1.f - z)*n;
  }
  __syncthreads();

  const float4* swv4 = (const float4*)sW;
  for (int t=1;t<5;t++){
    float acc[3][2][4];
#pragma unroll
    for (int gate=0;gate<3;gate++)
#pragma unroll
      for (int s=0;s<2;s++){ acc[gate][s][0]=0.f;acc[gate][s][1]=0.f;acc[gate][s][2]=0.f;acc[gate][s][3]=0.f; }
#pragma unroll
    for (int kt=0;kt<16;kt++){
      int k0 = kt*8 + tig;
      unsigned a0 = f2tf(sH[g*128     + k0]);
      unsigned a1 = f2tf(sH[(g+8)*128 + k0]);
      unsigned a2 = f2tf(sH[g*128     + k0+4]);
      unsigned a3 = f2tf(sH[(g+8)*128 + k0+4]);
#pragma unroll
      for (int gate=0;gate<3;gate++){
        int pr = gate*8 + warp;
        float4 bv = swv4[(kt*24 + pr)*32 + lane];
        mma8(acc[gate][0], a0,a1,a2,a3, __float_as_uint(bv.x), __float_as_uint(bv.y));
        mma8(acc[gate][1], a0,a1,a2,a3, __float_as_uint(bv.z), __float_as_uint(bv.w));
      }
    }
    __syncthreads();
    const float* ig0 = g_IG + (((long)(b0+g))*5   + t)*384;
    const float* ig1 = g_IG + (((long)(b0+g+8))*5 + t)*384;
#pragma unroll
    for (int s=0;s<2;s++){
#pragma unroll
      for (int cc=0;cc<2;cc++){
        int j = warp*16 + s*8 + tig*2 + cc;
        {
          float r = sigf(ig0[j]       + acc[0][s][cc] + sB[j]);
          float z = sigf(ig0[128+j]   + acc[1][s][cc] + sB[128+j]);
          float n = tanhf_fast(ig0[256+j] + r*(acc[2][s][cc] + sB[256+j]));
          float hp = sH[g*128 + j];
          sH[g*128 + j] = (1.f-z)*n + z*hp;
        }
        {
          float r = sigf(ig1[j]       + acc[0][s][cc+2] + sB[j]);
          float z = sigf(ig1[128+j]   + acc[1][s][cc+2] + sB[128+j]);
          float n = tanhf_fast(ig1[256+j] + r*(acc[2][s][cc+2] + sB[256+j]));
          float hp = sH[(g+8)*128 + j];
          sH[(g+8)*128 + j] = (1.f-z)*n + z*hp;
        }
      }
    }
    __syncthreads();
  }

  // ================= fused per-batch prep =================
  const int L0 = lens[b0+g], L1 = lens[b0+8+g];
  const float* lt0 = txe + ((long)(b0+g)*L_   + L0-1)*128;
  const float* lt1 = txe + ((long)(b0+8+g)*L_ + L1-1)*128;
  const float* li0 = ide + ((long)(b0+g)*L_   + L0-1)*64;
  const float* li1 = ide + ((long)(b0+8+g)*L_ + L1-1)*64;
  const float* h0  = sH + g*128;
  const float* h1  = sH + (g+8)*128;

  // CT: M=16, N=128 (warp w owns n2=w), K=256 = [lt | h]
  {
    float acc[2][4];
    acc[0][0]=0.f;acc[0][1]=0.f;acc[0][2]=0.f;acc[0][3]=0.f;
    acc[1][0]=0.f;acc[1][1]=0.f;acc[1][2]=0.f;acc[1][3]=0.f;
    const float4* bp = (const float4*)g_WCT;
#pragma unroll
    for (int kt=0;kt<32;kt++){
      int k0 = kt*8 + tig, k4 = k0+4;
      unsigned a0 = f2tf(k0<128 ? lt0[k0] : h0[k0-128]);
      unsigned a2 = f2tf(k4<128 ? lt0[k4] : h0[k4-128]);
      unsigned a1 = f2tf(k0<128 ? lt1[k0] : h1[k0-128]);
      unsigned a3 = f2tf(k4<128 ? lt1[k4] : h1[k4-128]);
      float4 bv = bp[(kt*8 + warp)*32 + lane];
      mma8(acc[0], a0,a1,a2,a3, __float_as_uint(bv.x), __float_as_uint(bv.y));
      mma8(acc[1], a0,a1,a2,a3, __float_as_uint(bv.z), __float_as_uint(bv.w));
    }
#pragma unroll
    for (int s=0;s<2;s++){
      int j = (2*warp+s)*8 + 2*tig;
      float* o0 = g_CT + (long)(b0+g)*128 + j;
      float* o1 = g_CT + (long)(b0+8+g)*128 + j;
      o0[0] = acc[s][0]+sbt[j]; o0[1] = acc[s][1]+sbt[j+1];
      o1[0] = acc[s][2]+sbt[j]; o1[1] = acc[s][3]+sbt[j+1];
    }
  }
  // CI: K=192 = [lid | h]
  {
    float acc[2][4];
    acc[0][0]=0.f;acc[0][1]=0.f;acc[0][2]=0.f;acc[0][3]=0.f;
    acc[1][0]=0.f;acc[1][1]=0.f;acc[1][2]=0.f;acc[1][3]=0.f;
    const float4* bp = (const float4*)g_WCI;
#pragma unroll
    for (int kt=0;kt<24;kt++){
      int k0 = kt*8 + tig, k4 = k0+4;
      unsigned a0 = f2tf(k0<64 ? li0[k0] : h0[k0-64]);
      unsigned a2 = f2tf(k4<64 ? li0[k4] : h0[k4-64]);
      unsigned a1 = f2tf(k0<64 ? li1[k0] : h1[k0-64]);
      unsigned a3 = f2tf(k4<64 ? li1[k4] : h1[k4-64]);
      float4 bv = bp[(kt*8 + warp)*32 + lane];
      mma8(acc[0], a0,a1,a2,a3, __float_as_uint(bv.x), __float_as_uint(bv.y));
      mma8(acc[1], a0,a1,a2,a3, __float_as_uint(bv.z), __float_as_uint(bv.w));
    }
#pragma unroll
    for (int s=0;s<2;s++){
      int j = (2*warp+s)*8 + 2*tig;
      float* o0 = g_CI + (long)(b0+g)*128 + j;
      float* o1 = g_CI + (long)(b0+8+g)*128 + j;
      o0[0] = acc[s][0]+sbi[j]; o0[1] = acc[s][1]+sbi[j+1];
      o1[0] = acc[s][2]+sbi[j]; o1[1] = acc[s][3]+sbi[j+1];
    }
  }
  // alpha: N=64 (warps 0-3, n2=warp), K=128 = h ; a1s reuses sW space
  float (*a1s)[64] = (float(*)[64])sW;
  float (*lg)[3]   = (float(*)[3])(sW + 16*64);
  {
    if (warp < 4){
      float acc[2][4];
      acc[0][0]=0.f;acc[0][1]=0.f;acc[0][2]=0.f;acc[0][3]=0.f;
      acc[1][0]=0.f;acc[1][1]=0.f;acc[1][2]=0.f;acc[1][3]=0.f;
      const float4* bp = (const float4*)g_WA;
#pragma unroll
      for (int kt=0;kt<16;kt++){
        int k0 = kt*8 + tig;
        unsigned a0 = f2tf(h0[k0]), a2 = f2tf(h0[k0+4]);
        unsigned a1 = f2tf(h1[k0]), a3 = f2tf(h1[k0+4]);
        float4 bv = bp[(kt*4 + warp)*32 + lane];
        mma8(acc[0], a0,a1,a2,a3, __float_as_uint(bv.x), __float_as_uint(bv.y));
        mma8(acc[1], a0,a1,a2,a3, __float_as_uint(bv.z), __float_as_uint(bv.w));
      }
#pragma unroll
      for (int s=0;s<2;s++){
        int u = (2*warp+s)*8 + 2*tig;
        a1s[g][u]     = fmaxf(acc[s][0]+sba[u],0.f);
        a1s[g][u+1]   = fmaxf(acc[s][1]+sba[u+1],0.f);
        a1s[g+8][u]   = fmaxf(acc[s][2]+sba[u],0.f);
        a1s[g+8][u+1] = fmaxf(acc[s][3]+sba[u+1],0.f);
      }
    }
    __syncthreads();
    if (tid < 48){
      int bb = tid/3, gg = tid%3;
      float s = sba2[gg];
      const float* w = swa2 + gg*64;
      for (int u=0;u<64;u++) s += w[u]*a1s[bb][u];
      lg[bb][gg] = s;
    }
    __syncthreads();
    if (tid < 16){
      float l0=lg[tid][0], l1=lg[tid][1], l2=lg[tid][2];
      float m = fmaxf(l0, fmaxf(l1,l2));
      float e0=__expf(l0-m), e1=__expf(l1-m), e2=__expf(l2-m);
      float inv = 1.f/(e0+e1+e2);
      g_AL[(b0+tid)*3+0]=e0*inv; g_AL[(b0+tid)*3+1]=e1*inv; g_AL[(b0+tid)*3+2]=e2*inv;
    }
  }
}

// ---- fused scorer (bf16 m16n8k16): 2 batches/block, n2-outer, B shared ----
__global__ __launch_bounds__(256, 2) void k_score(
    const float* __restrict__ ctxe, const float* __restrict__ cide,
    const int* __restrict__ cids, const float* __restrict__ co,
    const float* __restrict__ Wt2, const float* __restrict__ bt2,
    const float* __restrict__ Wi2, const float* __restrict__ bi2,
    const float* __restrict__ betac, const float* __restrict__ lTc,
    const float* __restrict__ lTt, const float* __restrict__ lTi,
    float* __restrict__ out)
{
  __shared__ float ctv[2][128], civ[2][128], w2t[128], w2i[128];
  __shared__ float sco[2][3][128];
  __shared__ float mx3[2][3], inv3[2][3], sS[2];
  __shared__ float mixv[2][128];
  const int bA = 2*blockIdx.x, bB = bA + 1;
  const int tid = threadIdx.x;
  const int warp = tid>>5, lane = tid&31;
  const int g = lane>>2, tig = lane&3;
  const int r0 = warp*16 + g, r1 = r0 + 8;

  if (tid < 128){
    ctv[0][tid]=g_CT[bA*128+tid]; civ[0][tid]=g_CI[bA*128+tid];
    w2t[tid]=Wt2[tid];            w2i[tid]=Wi2[tid];
  } else {
    int t = tid-128;
    ctv[1][t]=g_CT[bB*128+t];     civ[1][t]=g_CI[bB*128+t];
  }
  const float bc = betac[0], eTc = expf(lTc[0]);
  if (tid < 100){
    long li = g_LI[bA];
    sco[0][0][tid] = co[li*V_ + cids[(long)bA*C_+tid]] * bc / eTc;
  } else if (tid >= 128 && tid < 228){
    int t = tid-128;
    long li = g_LI[bB];
    sco[1][0][t] = co[li*V_ + cids[(long)bB*C_+t]] * bc / eTc;
  }
  const float Tt = expf(lTt[0]), Ti = expf(lTi[0]);
  __syncthreads();

  // ---- text pass: K=128; A prefetched (both batches), n2 outer, B shared ----
  {
    const float* E0 = ctxe + (long)bA*C_*128;
    const float* E1 = ctxe + (long)bB*C_*128;
    unsigned aA[8][4], aB[8][4];
#pragma unroll
    for (int kt=0;kt<8;kt++){
      const int k0 = kt*16 + tig*2;
      aA[kt][0]=0u; aA[kt][1]=0u; aA[kt][2]=0u; aA[kt][3]=0u;
      aB[kt][0]=0u; aB[kt][1]=0u; aB[kt][2]=0u; aB[kt][3]=0u;
      if (r0 < C_){
        float2 x = *(const float2*)(E0 + (long)r0*128 + k0);
        float2 y = *(const float2*)(E0 + (long)r0*128 + k0 + 8);
        aA[kt][0] = pkbf(x.x,x.y); aA[kt][2] = pkbf(y.x,y.y);
        x = *(const float2*)(E1 + (long)r0*128 + k0);
        y = *(const float2*)(E1 + (long)r0*128 + k0 + 8);
        aB[kt][0] = pkbf(x.x,x.y); aB[kt][2] = pkbf(y.x,y.y);
      }
      if (r1 < C_){
        float2 x = *(const float2*)(E0 + (long)r1*128 + k0);
        float2 y = *(const float2*)(E0 + (long)r1*128 + k0 + 8);
        aA[kt][1] = pkbf(x.x,x.y); aA[kt][3] = pkbf(y.x,y.y);
        x = *(const float2*)(E1 + (long)r1*128 + k0);
        y = *(const float2*)(E1 + (long)r1*128 + k0 + 8);
        aB[kt][1] = pkbf(x.x,x.y); aB[kt][3] = pkbf(y.x,y.y);
      }
    }
    const uint4* bp = (const uint4*)g_WT16;
    float pA0=0.f, pA1=0.f, pB0=0.f, pB1=0.f;
#pragma unroll
    for (int n2=0;n2<8;n2++){
      float cA0[4]={0.f,0.f,0.f,0.f}, cA1[4]={0.f,0.f,0.f,0.f};
      float cB0[4]={0.f,0.f,0.f,0.f}, cB1[4]={0.f,0.f,0.f,0.f};
#pragma unroll
      for (int kt=0;kt<8;kt++){
        uint4 bv = bp[(kt*8 + n2)*32 + lane];
        mma16(cA0, aA[kt][0],aA[kt][1],aA[kt][2],aA[kt][3], bv.x, bv.y);
        mma16(cA1, aA[kt][0],aA[kt][1],aA[kt][2],aA[kt][3], bv.z, bv.w);
        mma16(cB0, aB[kt][0],aB[kt][1],aB[kt][2],aB[kt][3], bv.x, bv.y);
        mma16(cB1, aB[kt][0],aB[kt][1],aB[kt][2],aB[kt][3], bv.z, bv.w);
      }
      {
        int j0 = (2*n2)*8 + 2*tig;
        float w0=w2t[j0], w1=w2t[j0+1];
        float c0=ctv[0][j0], c1=ctv[0][j0+1];
        pA0 += w0*fmaxf(c0+cA0[0],0.f) + w1*fmaxf(c1+cA0[1],0.f);
        pA1 += w0*fmaxf(c0+cA0[2],0.f) + w1*fmaxf(c1+cA0[3],0.f);
        c0=ctv[1][j0]; c1=ctv[1][j0+1];
        pB0 += w0*fmaxf(c0+cB0[0],0.f) + w1*fmaxf(c1+cB0[1],0.f);
        pB1 += w0*fmaxf(c0+cB0[2],0.f) + w1*fmaxf(c1+cB0[3],0.f);
      }
      {
        int j0 = (2*n2+1)*8 + 2*tig;
        float w0=w2t[j0], w1=w2t[j0+1];
        float c0=ctv[0][j0], c1=ctv[0][j0+1];
        pA0 += w0*fmaxf(c0+cA1[0],0.f) + w1*fmaxf(c1+cA1[1],0.f);
        pA1 += w0*fmaxf(c0+cA1[2],0.f) + w1*fmaxf(c1+cA1[3],0.f);
        c0=ctv[1][j0]; c1=ctv[1][j0+1];
        pB0 += w0*fmaxf(c0+cB1[0],0.f) + w1*fmaxf(c1+cB1[1],0.f);
        pB1 += w0*fmaxf(c0+cB1[2],0.f) + w1*fmaxf(c1+cB1[3],0.f);
      }
    }
    pA0 += __shfl_xor_sync(0xffffffffu,pA0,1); pA0 += __shfl_xor_sync(0xffffffffu,pA0,2);
    pA1 += __shfl_xor_sync(0xffffffffu,pA1,1); pA1 += __shfl_xor_sync(0xffffffffu,pA1,2);
    pB0 += __shfl_xor_sync(0xffffffffu,pB0,1); pB0 += __shfl_xor_sync(0xffffffffu,pB0,2);
    pB1 += __shfl_xor_sync(0xffffffffu,pB1,1); pB1 += __shfl_xor_sync(0xffffffffu,pB1,2);
    if (tig==0){
      if (r0 < C_){ sco[0][1][r0] = (pA0 + bt2[0]) / Tt; sco[1][1][r0] = (pB0 + bt2[0]) / Tt; }
      if (r1 < C_){ sco[0][1][r1] = (pA1 + bt2[0]) / Tt; sco[1][1][r1] = (pB1 + bt2[0]) / Tt; }
    }
  }
  // ---- id pass: K=64 ----
  {
    const float* E0 = cide + (long)bA*C_*64;
    const float* E1 = cide + (long)bB*C_*64;
    unsigned aA[4][4], aB[4][4];
#pragma unroll
    for (int kt=0;kt<4;kt++){
      const int k0 = kt*16 + tig*2;
      aA[kt][0]=0u; aA[kt][1]=0u; aA[kt][2]=0u; aA[kt][3]=0u;
      aB[kt][0]=0u; aB[kt][1]=0u; aB[kt][2]=0u; aB[kt][3]=0u;
      if (r0 < C_){
        float2 x = *(const float2*)(E0 + (long)r0*64 + k0);
        float2 y = *(const float2*)(E0 + (long)r0*64 + k0 + 8);
        aA[kt][0] = pkbf(x.x,x.y); aA[kt][2] = pkbf(y.x,y.y);
        x = *(const float2*)(E1 + (long)r0*64 + k0);
        y = *(const float2*)(E1 + (long)r0*64 + k0 + 8);
        aB[kt][0] = pkbf(x.x,x.y); aB[kt][2] = pkbf(y.x,y.y);
      }
      if (r1 < C_){
        float2 x = *(const float2*)(E0 + (long)r1*64 + k0);
        float2 y = *(const float2*)(E0 + (long)r1*64 + k0 + 8);
        aA[kt][1] = pkbf(x.x,x.y); aA[kt][3] = pkbf(y.x,y.y);
        x = *(const float2*)(E1 + (long)r1*64 + k0);
        y = *(const float2*)(E1 + (long)r1*64 + k0 + 8);
        aB[kt][1] = pkbf(x.x,x.y); aB[kt][3] = pkbf(y.x,y.y);
      }
    }
    const uint4* bp = (const uint4*)g_WI16;
    float pA0=0.f, pA1=0.f, pB0=0.f, pB1=0.f;
#pragma unroll
    for (int n2=0;n2<8;n2++){
      float cA0[4]={0.f,0.f,0.f,0.f}, cA1[4]={0.f,0.f,0.f,0.f};
      float cB0[4]={0.f,0.f,0.f,0.f}, cB1[4]={0.f,0.f,0.f,0.f};
#pragma unroll
      for (int kt=0;kt<4;kt++){
        uint4 bv = bp[(kt*8 + n2)*32 + lane];
        mma16(cA0, aA[kt][0],aA[kt][1],aA[kt][2],aA[kt][3], bv.x, bv.y);
        mma16(cA1, aA[kt][0],aA[kt][1],aA[kt][2],aA[kt][3], bv.z, bv.w);
        mma16(cB0, aB[kt][0],aB[kt][1],aB[kt][2],aB[kt][3], bv.x, bv.y);
        mma16(cB1, aB[kt][0],aB[kt][1],aB[kt][2],aB[kt][3], bv.z, bv.w);
      }
      {
        int j0 = (2*n2)*8 + 2*tig;
        float w0=w2i[j0], w1=w2i[j0+1];
        float c0=civ[0][j0], c1=civ[0][j0+1];
        pA0 += w0*fmaxf(c0+cA0[0],0.f) + w1*fmaxf(c1+cA0[1],0.f);
        pA1 += w0*fmaxf(c0+cA0[2],0.f) + w1*fmaxf(c1+cA0[3],0.f);
        c0=civ[1][j0]; c1=civ[1][j0+1];
        pB0 += w0*fmaxf(c0+cB0[0],0.f) + w1*fmaxf(c1+cB0[1],0.f);
        pB1 += w0*fmaxf(c0+cB0[2],0.f) + w1*fmaxf(c1+cB0[3],0.f);
      }
      {
        int j0 = (2*n2+1)*8 + 2*tig;
        float w0=w2i[j0], w1=w2i[j0+1];
        float c0=civ[0][j0], c1=civ[0][j0+1];
        pA0 += w0*fmaxf(c0+cA1[0],0.f) + w1*fmaxf(c1+cA1[1],0.f);
        pA1 += w0*fmaxf(c0+cA1[2],0.f) + w1*fmaxf(c1+cA1[3],0.f);
        c0=civ[1][j0]; c1=civ[1][j0+1];
        pB0 += w0*fmaxf(c0+cB1[0],0.f) + w1*fmaxf(c1+cB1[1],0.f);
        pB1 += w0*fmaxf(c0+cB1[2],0.f) + w1*fmaxf(c1+cB1[3],0.f);
      }
    }
    pA0 += __shfl_xor_sync(0xffffffffu,pA0,1); pA0 += __shfl_xor_sync(0xffffffffu,pA0,2);
    pA1 += __shfl_xor_sync(0xffffffffu,pA1,1); pA1 += __shfl_xor_sync(0xffffffffu,pA1,2);
    pB0 += __shfl_xor_sync(0xffffffffu,pB0,1); pB0 += __shfl_xor_sync(0xffffffffu,pB0,2);
    pB1 += __shfl_xor_sync(0xffffffffu,pB1,1); pB1 += __shfl_xor_sync(0xffffffffu,pB1,2);
    if (tig==0){
      if (r0 < C_){ sco[0][2][r0] = (pA0 + bi2[0]) / Ti; sco[1][2][r0] = (pB0 + bi2[0]) / Ti; }
      if (r1 < C_){ sco[0][2][r1] = (pA1 + bi2[0]) / Ti; sco[1][2][r1] = (pB1 + bi2[0]) / Ti; }
    }
  }
  __syncthreads();

  // 6 softmaxes: warp w<6 handles (batch = w/3, channel = w%3)
  if (warp < 6){
    int bs = warp/3, chn = warp%3;
    float m = -1e30f;
    for (int q=lane;q<C_;q+=32) m = fmaxf(m, sco[bs][chn][q]);
    m = wmax(m);
    float s = 0.f;
    for (int q=lane;q<C_;q+=32) s += __expf(sco[bs][chn][q]-m);
    s = wsum(s);
    if (lane==0){ mx3[bs][chn]=m; inv3[bs][chn]=1.f/s; }
  }
  __syncthreads();
  if (tid < 100){
    const float a0=g_AL[bA*3], a1=g_AL[bA*3+1], a2=g_AL[bA*3+2];
    mixv[0][tid] = 0.01f
      + a0*__expf(sco[0][0][tid]-mx3[0][0])*inv3[0][0]
      + a1*__expf(sco[0][1][tid]-mx3[0][1])*inv3[0][1]
      + a2*__expf(sco[0][2][tid]-mx3[0][2])*inv3[0][2];
  } else if (tid >= 128 && tid < 228){
    int t = tid-128;
    const float a0=g_AL[bB*3], a1=g_AL[bB*3+1], a2=g_AL[bB*3+2];
    mixv[1][t] = 0.01f
      + a0*__expf(sco[1][0][t]-mx3[1][0])*inv3[1][0]
      + a1*__expf(sco[1][1][t]-mx3[1][1])*inv3[1][1]
      + a2*__expf(sco[1][2][t]-mx3[1][2])*inv3[1][2];
  }
  __syncthreads();
  if (warp < 2){
    float s = 0.f;
    for (int q=lane;q<C_;q+=32) s += mixv[warp][q];
    s = wsum(s);
    if (lane==0) sS[warp] = 1.f/s;
  }
  __syncthreads();
  if (tid < 100) out[(long)bA*C_ + tid] = mixv[0][tid]*sS[0];
  else if (tid >= 128 && tid < 228) out[(long)bB*C_ + (tid-128)] = mixv[1][tid-128]*sS[1];
}

extern "C" void kernel_launch(void* const* d_in, const int* in_sizes, int n_in,
                              void* d_out, int out_size) {
  const int*   sitems = (const int*)  d_in[0];
  const float* ide    = (const float*)d_in[1];
  const float* txe    = (const float*)d_in[2];
  const int*   lens   = (const int*)  d_in[3];
  const int*   cids   = (const int*)  d_in[4];
  const float* cide   = (const float*)d_in[5];
  const float* ctxe   = (const float*)d_in[6];
  const float* co     = (const float*)d_in[7];
  const float* Wih    = (const float*)d_in[8];
  const float* Whh    = (const float*)d_in[9];
  const float* bih    = (const float*)d_in[10];
  const float* bhh    = (const float*)d_in[11];
  const float* Wt1    = (const float*)d_in[12];
  const float* bt1    = (const float*)d_in[13];
  const float* Wt2    = (const float*)d_in[14];
  const float* bt2    = (const float*)d_in[15];
  const float* Wi1    = (const float*)d_in[16];
  const float* bi1    = (const float*)d_in[17];
  const float* Wi2    = (const float*)d_in[18];
  const float* bi2    = (const float*)d_in[19];
  const float* Wa1    = (const float*)d_in[20];
  const float* ba1    = (const float*)d_in[21];
  const float* Wa2    = (const float*)d_in[22];
  const float* ba2    = (const float*)d_in[23];
  // d_in[24] = Wstab: unused (P_stable is uniform = 1/C exactly)
  const float* betac  = (const float*)d_in[25];
  const float* lTc    = (const float*)d_in[26];
  const float* lTt    = (const float*)d_in[27];
  const float* lTi    = (const float*)d_in[28];
  float* out = (float*)d_out;

  const int GRU_SMEM = (49152 + 2048 + 384 + 128 + 128 + 64 + 192 + 4) * 4;
  cudaFuncSetAttribute(k_gruall, cudaFuncAttributeMaxDynamicSharedMemorySize, GRU_SMEM);
  // maximize L1D carveout for the weight-streaming kernels (tiny static smem)
  cudaFuncSetAttribute(k_score, cudaFuncAttributePreferredSharedMemoryCarveout,
                       cudaSharedmemCarveoutMaxL1);
  cudaFuncSetAttribute(k_ig, cudaFuncAttributePreferredSharedMemoryCarveout,
                       cudaSharedmemCarveoutMaxL1);

  const int WPREP_N = 73728+49152+32768+24576+8192+8192+4096;
  k_wprep<<<(WPREP_N+255)/256, 256>>>(Wih, Whh, Wt1, Wi1, Wa1);
  k_ig<<<dim3(80,3), 256>>>(ide, txe, lens, bih);
  k_gruall<<<128, 256, GRU_SMEM>>>(bhh, ide, txe, lens, sitems,
                                   bt1, bi1, ba1, Wa2, ba2);
  k_score<<<B_/2, 256>>>(ctxe, cide, cids, co, Wt2, bt2, Wi2, bi2,
                         betac, lTc, lTt, lTi, out);
}

// round 17
// speedup vs baseline: 1.2765x; 1.1908x over previous
#include <cuda_runtime.h>
#include <cuda_bf16.h>
#include <math.h>

#define B_  2048
#define L_  200
#define C_  100
#define V_  2000

// ---------------- scratch ----------------
__device__ float g_IG  [B_*5*384];
__device__ float g_CT  [B_*128];
__device__ float g_CI  [B_*128];
__device__ float g_AL  [B_*3];
__device__ float g_WIHf[73728];        // W_ih (N=384,K=192) tf32 frag order
__device__ float g_WHHf[49152];        // W_hh (N=384,K=128) tf32 frag order
__device__ float g_WCT [32768];        // [Wt1 src | Wt1 h]  (N=128,K=256) tf32 frag
__device__ float g_WCI [24576];        // [Wi1 src | Wi1 h]  (N=128,K=192) tf32 frag
__device__ float g_WA  [8192];         // Wa1 (N=64,K=128) tf32 frag
__device__ unsigned g_WT16[8192];      // Wt1 mid slab bf16 m16n8k16 frag (32KB)
__device__ unsigned g_WI16[4096];      // Wi1 mid slab bf16 m16n8k16 frag (16KB)
__device__ int   g_LI  [B_];

__device__ __forceinline__ float sigf(float x){ return 1.0f/(1.0f+__expf(-x)); }
__device__ __forceinline__ float tanhf_fast(float x){
  x = fminf(fmaxf(x,-15.f),15.f);
  float e = __expf(2.f*x);
  return (e-1.f)/(e+1.f);
}
__device__ __forceinline__ float wsum(float v){
#pragma unroll
  for (int o=16;o;o>>=1) v += __shfl_xor_sync(0xffffffffu, v, o);
  return v;
}
__device__ __forceinline__ float wmax(float v){
#pragma unroll
  for (int o=16;o;o>>=1) v = fmaxf(v, __shfl_xor_sync(0xffffffffu, v, o));
  return v;
}
__device__ __forceinline__ unsigned f2tf(float x){
  unsigned r; asm("cvt.rna.tf32.f32 %0, %1;" : "=r"(r) : "f"(x)); return r;
}
__device__ __forceinline__ unsigned pkbf(float lo, float hi){
  __nv_bfloat162 h = __floats2bfloat162_rn(lo, hi);
  return *(unsigned*)&h;
}
__device__ __forceinline__ void mma8(float* d,
    unsigned a0, unsigned a1, unsigned a2, unsigned a3,
    unsigned b0, unsigned b1){
  asm volatile(
    "mma.sync.aligned.m16n8k8.row.col.f32.tf32.tf32.f32 "
    "{%0,%1,%2,%3},{%4,%5,%6,%7},{%8,%9},{%0,%1,%2,%3};\n"
    : "+f"(d[0]),"+f"(d[1]),"+f"(d[2]),"+f"(d[3])
    : "r"(a0),"r"(a1),"r"(a2),"r"(a3),"r"(b0),"r"(b1));
}
__device__ __forceinline__ void mma16(float* d,
    unsigned a0, unsigned a1, unsigned a2, unsigned a3,
    unsigned b0, unsigned b1){
  asm volatile(
    "mma.sync.aligned.m16n8k16.row.col.f32.bf16.bf16.f32 "
    "{%0,%1,%2,%3},{%4,%5,%6,%7},{%8,%9},{%0,%1,%2,%3};\n"
    : "+f"(d[0]),"+f"(d[1]),"+f"(d[2]),"+f"(d[3])
    : "r"(a0),"r"(a1),"r"(a2),"r"(a3),"r"(b0),"r"(b1));
}

// decode tf32 fragment-order flat index -> (j,k) for weight W[N][K]
__device__ __forceinline__ void frag_jk(int idx, int N, int* jj, int* kk){
  int c = idx & 3, lane = (idx>>2)&31;
  int P = N >> 4;
  int pr = (idx>>7) % P;
  int kt = idx / (128*P);
  int nt = 2*pr + (c>>1), p = c&1;
  *jj = nt*8 + (lane>>2);
  *kk = kt*8 + (lane&3) + 4*p;
}
// decode bf16 m16n8k16 frag (uint4-of-n-pairs) flat uint index -> (j, k0)
__device__ __forceinline__ void frag16_jk(int idx, int* jj, int* kk){
  int w = idx & 3, lane = (idx>>2)&31, n2 = (idx>>7)&7, kt = idx>>10;
  int n = 2*n2 + (w>>1);
  *jj = n*8 + (lane>>2);
  *kk = kt*16 + (lane&3)*2 + (w&1)*8;
}

// ---- prepare all fragment-ordered weights ----
__global__ void k_wprep(const float* __restrict__ Wih, const float* __restrict__ Whh,
                        const float* __restrict__ Wt1, const float* __restrict__ Wi1,
                        const float* __restrict__ Wa1){
  int idx = blockIdx.x*blockDim.x + threadIdx.x;
  int j, k;
  int off = 0;
  if (idx < (off += 73728)){                       // Wih: N=384,K=192
    frag_jk(idx, 384, &j, &k);
    g_WIHf[idx] = __uint_as_float(f2tf(Wih[(long)j*192 + k]));
    return;
  }
  if (idx < (off + 49152)){                        // Whh: N=384,K=128
    int i2 = idx - off;
    frag_jk(i2, 384, &j, &k);
    g_WHHf[i2] = __uint_as_float(f2tf(Whh[(long)j*128 + k]));
    return;
  }
  off += 49152;
  if (idx < (off + 32768)){                        // WCT: N=128,K=256
    int i2 = idx - off;
    frag_jk(i2, 128, &j, &k);
    float v = (k < 128) ? Wt1[(long)j*384 + k] : Wt1[(long)j*384 + 256 + (k-128)];
    g_WCT[i2] = __uint_as_float(f2tf(v));
    return;
  }
  off += 32768;
  if (idx < (off + 24576)){                        // WCI: N=128,K=192
    int i2 = idx - off;
    frag_jk(i2, 128, &j, &k);
    float v = (k < 64) ? Wi1[(long)j*256 + k] : Wi1[(long)j*256 + 128 + (k-64)];
    g_WCI[i2] = __uint_as_float(f2tf(v));
    return;
  }
  off += 24576;
  if (idx < (off + 8192)){                         // WA: N=64,K=128
    int i2 = idx - off;
    frag_jk(i2, 64, &j, &k);
    g_WA[i2] = __uint_as_float(f2tf(Wa1[(long)j*128 + k]));
    return;
  }
  off += 8192;
  if (idx < (off + 8192)){                         // WT16 bf16: N=128,K=128
    int i2 = idx - off;
    frag16_jk(i2, &j, &k);
    g_WT16[i2] = pkbf(Wt1[(long)j*384 + 128 + k], Wt1[(long)j*384 + 128 + k + 1]);
    return;
  }
  off += 8192;
  if (idx < (off + 4096)){                         // WI16 bf16: N=128,K=64
    int i2 = idx - off;
    frag16_jk(i2, &j, &k);
    g_WI16[i2] = pkbf(Wi1[(long)j*256 + 64 + k], Wi1[(long)j*256 + 64 + k + 1]);
    return;
  }
}

// ---- input-gate GEMM (tf32): IG[m][n] = x_m · Wih[n] + bih[n] ----
// grid = (80, 3): blockIdx.y selects the 128-wide gate chunk
__global__ __launch_bounds__(256) void k_ig(
    const float* __restrict__ ide, const float* __restrict__ txe,
    const int* __restrict__ lens, const float* __restrict__ bih)
{
  __shared__ float sB[384];
  const int tid = threadIdx.x, warp = tid>>5, lane = tid&31;
  const int g = lane>>2, tig = lane&3;
  const int ch = blockIdx.y;
  for (int i=tid; i<384; i+=256) sB[i] = bih[i];
  const int r0 = blockIdx.x*128 + warp*16 + g;
  const int r1 = r0 + 8;
  int b0 = r0/5, t0 = r0 - 5*b0;  int p0 = lens[b0] - 5 + t0;
  int b1 = r1/5, t1 = r1 - 5*b1;  int p1 = lens[b1] - 5 + t1;
  const float* id0 = ide + ((long)b0*L_ + p0)*64;
  const float* tx0 = txe + ((long)b0*L_ + p0)*128;
  const float* id1 = ide + ((long)b1*L_ + p1)*64;
  const float* tx1 = txe + ((long)b1*L_ + p1)*128;
  __syncthreads();

  const float4* bp = (const float4*)g_WIHf;
  float acc[16][4];
#pragma unroll
  for (int nt=0;nt<16;nt++){ acc[nt][0]=0.f;acc[nt][1]=0.f;acc[nt][2]=0.f;acc[nt][3]=0.f; }
#pragma unroll
  for (int kt=0;kt<24;kt++){
    int k0 = kt*8 + tig, k4 = k0+4;
    unsigned a0 = f2tf(k0<64 ? id0[k0] : tx0[k0-64]);
    unsigned a2 = f2tf(k4<64 ? id0[k4] : tx0[k4-64]);
    unsigned a1 = f2tf(k0<64 ? id1[k0] : tx1[k0-64]);
    unsigned a3 = f2tf(k4<64 ? id1[k4] : tx1[k4-64]);
#pragma unroll
    for (int n2=0;n2<8;n2++){
      float4 bv = bp[(kt*24 + ch*8 + n2)*32 + lane];
      mma8(acc[2*n2],   a0,a1,a2,a3, __float_as_uint(bv.x), __float_as_uint(bv.y));
      mma8(acc[2*n2+1], a0,a1,a2,a3, __float_as_uint(bv.z), __float_as_uint(bv.w));
    }
  }
#pragma unroll
  for (int nt=0;nt<16;nt++){
    int j = ch*128 + nt*8 + 2*tig;
    float* o0 = g_IG + (long)r0*384 + j;
    float* o1 = g_IG + (long)r1*384 + j;
    o0[0] = acc[nt][0]+sB[j]; o0[1] = acc[nt][1]+sB[j+1];
    o1[0] = acc[nt][2]+sB[j]; o1[1] = acc[nt][3]+sB[j+1];
  }
}

// ---- persistent fused GRU (5 steps) + per-batch prep (ct/ci/alpha) ----
__global__ __launch_bounds__(256) void k_gruall(
    const float* __restrict__ bhh,
    const float* __restrict__ ide, const float* __restrict__ txe,
    const int* __restrict__ lens, const int* __restrict__ sitems,
    const float* __restrict__ bt1, const float* __restrict__ bi1,
    const float* __restrict__ ba1, const float* __restrict__ Wa2,
    const float* __restrict__ ba2)
{
  extern __shared__ float sm[];
  float* sW  = sm;                  // 49152 (W_hh frags; reused after GRU)
  float* sH  = sm + 49152;          // 2048
  float* sB  = sm + 49152+2048;     // 384
  float* sbt = sB + 384;            // 128
  float* sbi = sbt + 128;           // 128
  float* sba = sbi + 128;           // 64
  float* swa2= sba + 64;            // 192
  float* sba2= swa2 + 192;          // 4 (3 used)
  const int tid = threadIdx.x, warp = tid>>5, lane = tid&31;
  const int g = lane>>2, tig = lane&3;
  const int b0 = blockIdx.x*16;

  {
    const float4* gw = (const float4*)g_WHHf;
    float4* swv = (float4*)sW;
    for (int i=tid;i<12288;i+=256) swv[i] = gw[i];
  }
  for (int i=tid;i<384;i+=256) sB[i] = bhh[i];
  if (tid < 128){ sbt[tid] = bt1[tid]; sbi[tid] = bi1[tid]; }
  else if (tid < 192) sba[tid-128] = ba1[tid-128];
  else if (tid < 195) sba2[tid-192] = ba2[tid-192];
  for (int i=tid;i<192;i+=256) swa2[i] = Wa2[i];
  if (tid < 16) g_LI[b0+tid] = sitems[(long)(b0+tid)*L_ + lens[b0+tid]-1];
  __syncthreads();

  // step 0
  for (int i=tid;i<2048;i+=256){
    int bb = i>>7, j = i&127;
    const float* ig = g_IG + ((long)(b0+bb)*5)*384;
    float r = sigf(ig[j]       + sB[j]);
    float z = sigf(ig[128+j]   + sB[128+j]);
    float n = tanhf_fast(ig[256+j] + r*sB[256+j]);
    sH[i] = (1.f - z)*n;
  }
  __syncthreads();

  const float4* swv4 = (const float4*)sW;
  for (int t=1;t<5;t++){
    float acc[3][2][4];
#pragma unroll
    for (int gate=0;gate<3;gate++)
#pragma unroll
      for (int s=0;s<2;s++){ acc[gate][s][0]=0.f;acc[gate][s][1]=0.f;acc[gate][s][2]=0.f;acc[gate][s][3]=0.f; }
#pragma unroll
    for (int kt=0;kt<16;kt++){
      int k0 = kt*8 + tig;
      unsigned a0 = f2tf(sH[g*128     + k0]);
      unsigned a1 = f2tf(sH[(g+8)*128 + k0]);
      unsigned a2 = f2tf(sH[g*128     + k0+4]);
      unsigned a3 = f2tf(sH[(g+8)*128 + k0+4]);
#pragma unroll
      for (int gate=0;gate<3;gate++){
        int pr = gate*8 + warp;
        float4 bv = swv4[(kt*24 + pr)*32 + lane];
        mma8(acc[gate][0], a0,a1,a2,a3, __float_as_uint(bv.x), __float_as_uint(bv.y));
        mma8(acc[gate][1], a0,a1,a2,a3, __float_as_uint(bv.z), __float_as_uint(bv.w));
      }
    }
    __syncthreads();
    const float* ig0 = g_IG + (((long)(b0+g))*5   + t)*384;
    const float* ig1 = g_IG + (((long)(b0+g+8))*5 + t)*384;
#pragma unroll
    for (int s=0;s<2;s++){
#pragma unroll
      for (int cc=0;cc<2;cc++){
        int j = warp*16 + s*8 + tig*2 + cc;
        {
          float r = sigf(ig0[j]       + acc[0][s][cc] + sB[j]);
          float z = sigf(ig0[128+j]   + acc[1][s][cc] + sB[128+j]);
          float n = tanhf_fast(ig0[256+j] + r*(acc[2][s][cc] + sB[256+j]));
          float hp = sH[g*128 + j];
          sH[g*128 + j] = (1.f-z)*n + z*hp;
        }
        {
          float r = sigf(ig1[j]       + acc[0][s][cc+2] + sB[j]);
          float z = sigf(ig1[128+j]   + acc[1][s][cc+2] + sB[128+j]);
          float n = tanhf_fast(ig1[256+j] + r*(acc[2][s][cc+2] + sB[256+j]));
          float hp = sH[(g+8)*128 + j];
          sH[(g+8)*128 + j] = (1.f-z)*n + z*hp;
        }
      }
    }
    __syncthreads();
  }

  // ================= fused per-batch prep =================
  const int L0 = lens[b0+g], L1 = lens[b0+8+g];
  const float* lt0 = txe + ((long)(b0+g)*L_   + L0-1)*128;
  const float* lt1 = txe + ((long)(b0+8+g)*L_ + L1-1)*128;
  const float* li0 = ide + ((long)(b0+g)*L_   + L0-1)*64;
  const float* li1 = ide + ((long)(b0+8+g)*L_ + L1-1)*64;
  const float* h0  = sH + g*128;
  const float* h1  = sH + (g+8)*128;

  // CT: M=16, N=128 (warp w owns n2=w), K=256 = [lt | h]
  {
    float acc[2][4];
    acc[0][0]=0.f;acc[0][1]=0.f;acc[0][2]=0.f;acc[0][3]=0.f;
    acc[1][0]=0.f;acc[1][1]=0.f;acc[1][2]=0.f;acc[1][3]=0.f;
    const float4* bp = (const float4*)g_WCT;
#pragma unroll
    for (int kt=0;kt<32;kt++){
      int k0 = kt*8 + tig, k4 = k0+4;
      unsigned a0 = f2tf(k0<128 ? lt0[k0] : h0[k0-128]);
      unsigned a2 = f2tf(k4<128 ? lt0[k4] : h0[k4-128]);
      unsigned a1 = f2tf(k0<128 ? lt1[k0] : h1[k0-128]);
      unsigned a3 = f2tf(k4<128 ? lt1[k4] : h1[k4-128]);
      float4 bv = bp[(kt*8 + warp)*32 + lane];
      mma8(acc[0], a0,a1,a2,a3, __float_as_uint(bv.x), __float_as_uint(bv.y));
      mma8(acc[1], a0,a1,a2,a3, __float_as_uint(bv.z), __float_as_uint(bv.w));
    }
#pragma unroll
    for (int s=0;s<2;s++){
      int j = (2*warp+s)*8 + 2*tig;
      float* o0 = g_CT + (long)(b0+g)*128 + j;
      float* o1 = g_CT + (long)(b0+8+g)*128 + j;
      o0[0] = acc[s][0]+sbt[j]; o0[1] = acc[s][1]+sbt[j+1];
      o1[0] = acc[s][2]+sbt[j]; o1[1] = acc[s][3]+sbt[j+1];
    }
  }
  // CI: K=192 = [lid | h]
  {
    float acc[2][4];
    acc[0][0]=0.f;acc[0][1]=0.f;acc[0][2]=0.f;acc[0][3]=0.f;
    acc[1][0]=0.f;acc[1][1]=0.f;acc[1][2]=0.f;acc[1][3]=0.f;
    const float4* bp = (const float4*)g_WCI;
#pragma unroll
    for (int kt=0;kt<24;kt++){
      int k0 = kt*8 + tig, k4 = k0+4;
      unsigned a0 = f2tf(k0<64 ? li0[k0] : h0[k0-64]);
      unsigned a2 = f2tf(k4<64 ? li0[k4] : h0[k4-64]);
      unsigned a1 = f2tf(k0<64 ? li1[k0] : h1[k0-64]);
      unsigned a3 = f2tf(k4<64 ? li1[k4] : h1[k4-64]);
      float4 bv = bp[(kt*8 + warp)*32 + lane];
      mma8(acc[0], a0,a1,a2,a3, __float_as_uint(bv.x), __float_as_uint(bv.y));
      mma8(acc[1], a0,a1,a2,a3, __float_as_uint(bv.z), __float_as_uint(bv.w));
    }
#pragma unroll
    for (int s=0;s<2;s++){
      int j = (2*warp+s)*8 + 2*tig;
      float* o0 = g_CI + (long)(b0+g)*128 + j;
      float* o1 = g_CI + (long)(b0+8+g)*128 + j;
      o0[0] = acc[s][0]+sbi[j]; o0[1] = acc[s][1]+sbi[j+1];
      o1[0] = acc[s][2]+sbi[j]; o1[1] = acc[s][3]+sbi[j+1];
    }
  }
  // alpha: N=64 (warps 0-3, n2=warp), K=128 = h ; a1s reuses sW space
  float (*a1s)[64] = (float(*)[64])sW;
  float (*lg)[3]   = (float(*)[3])(sW + 16*64);
  {
    if (warp < 4){
      float acc[2][4];
      acc[0][0]=0.f;acc[0][1]=0.f;acc[0][2]=0.f;acc[0][3]=0.f;
      acc[1][0]=0.f;acc[1][1]=0.f;acc[1][2]=0.f;acc[1][3]=0.f;
      const float4* bp = (const float4*)g_WA;
#pragma unroll
      for (int kt=0;kt<16;kt++){
        int k0 = kt*8 + tig;
        unsigned a0 = f2tf(h0[k0]), a2 = f2tf(h0[k0+4]);
        unsigned a1 = f2tf(h1[k0]), a3 = f2tf(h1[k0+4]);
        float4 bv = bp[(kt*4 + warp)*32 + lane];
        mma8(acc[0], a0,a1,a2,a3, __float_as_uint(bv.x), __float_as_uint(bv.y));
        mma8(acc[1], a0,a1,a2,a3, __float_as_uint(bv.z), __float_as_uint(bv.w));
      }
#pragma unroll
      for (int s=0;s<2;s++){
        int u = (2*warp+s)*8 + 2*tig;
        a1s[g][u]     = fmaxf(acc[s][0]+sba[u],0.f);
        a1s[g][u+1]   = fmaxf(acc[s][1]+sba[u+1],0.f);
        a1s[g+8][u]   = fmaxf(acc[s][2]+sba[u],0.f);
        a1s[g+8][u+1] = fmaxf(acc[s][3]+sba[u+1],0.f);
      }
    }
    __syncthreads();
    if (tid < 48){
      int bb = tid/3, gg = tid%3;
      float s = sba2[gg];
      const float* w = swa2 + gg*64;
      for (int u=0;u<64;u++) s += w[u]*a1s[bb][u];
      lg[bb][gg] = s;
    }
    __syncthreads();
    if (tid < 16){
      float l0=lg[tid][0], l1=lg[tid][1], l2=lg[tid][2];
      float m = fmaxf(l0, fmaxf(l1,l2));
      float e0=__expf(l0-m), e1=__expf(l1-m), e2=__expf(l2-m);
      float inv = 1.f/(e0+e1+e2);
      g_AL[(b0+tid)*3+0]=e0*inv; g_AL[(b0+tid)*3+1]=e1*inv; g_AL[(b0+tid)*3+2]=e2*inv;
    }
  }
}

// ---- fused scorer (bf16 m16n8k16): 2 batches/block, n2-outer, B shared ----
__global__ __launch_bounds__(256, 2) void k_score(
    const float* __restrict__ ctxe, const float* __restrict__ cide,
    const int* __restrict__ cids, const float* __restrict__ co,
    const float* __restrict__ Wt2, const float* __restrict__ bt2,
    const float* __restrict__ Wi2, const float* __restrict__ bi2,
    const float* __restrict__ betac, const float* __restrict__ lTc,
    const float* __restrict__ lTt, const float* __restrict__ lTi,
    float* __restrict__ out)
{
  __shared__ float ctv[2][128], civ[2][128], w2t[128], w2i[128];
  __shared__ float sco[2][3][128];
  __shared__ float mx3[2][3], inv3[2][3], sS[2];
  __shared__ float mixv[2][128];
  const int bA = 2*blockIdx.x, bB = bA + 1;
  const int tid = threadIdx.x;
  const int warp = tid>>5, lane = tid&31;
  const int g = lane>>2, tig = lane&3;
  const int r0 = warp*16 + g, r1 = r0 + 8;

  if (tid < 128){
    ctv[0][tid]=g_CT[bA*128+tid]; civ[0][tid]=g_CI[bA*128+tid];
    w2t[tid]=Wt2[tid];            w2i[tid]=Wi2[tid];
  } else {
    int t = tid-128;
    ctv[1][t]=g_CT[bB*128+t];     civ[1][t]=g_CI[bB*128+t];
  }
  const float bc = betac[0], eTc = expf(lTc[0]);
  if (tid < 100){
    long li = g_LI[bA];
    sco[0][0][tid] = co[li*V_ + cids[(long)bA*C_+tid]] * bc / eTc;
  } else if (tid >= 128 && tid < 228){
    int t = tid-128;
    long li = g_LI[bB];
    sco[1][0][t] = co[li*V_ + cids[(long)bB*C_+t]] * bc / eTc;
  }
  const float Tt = expf(lTt[0]), Ti = expf(lTi[0]);
  __syncthreads();

  // ---- text pass: K=128; A prefetched (both batches), n2 outer, B shared ----
  {
    const float* E0 = ctxe + (long)bA*C_*128;
    const float* E1 = ctxe + (long)bB*C_*128;
    unsigned aA[8][4], aB[8][4];
#pragma unroll
    for (int kt=0;kt<8;kt++){
      const int k0 = kt*16 + tig*2;
      aA[kt][0]=0u; aA[kt][1]=0u; aA[kt][2]=0u; aA[kt][3]=0u;
      aB[kt][0]=0u; aB[kt][1]=0u; aB[kt][2]=0u; aB[kt][3]=0u;
      if (r0 < C_){
        float2 x = *(const float2*)(E0 + (long)r0*128 + k0);
        float2 y = *(const float2*)(E0 + (long)r0*128 + k0 + 8);
        aA[kt][0] = pkbf(x.x,x.y); aA[kt][2] = pkbf(y.x,y.y);
        x = *(const float2*)(E1 + (long)r0*128 + k0);
        y = *(const float2*)(E1 + (long)r0*128 + k0 + 8);
        aB[kt][0] = pkbf(x.x,x.y); aB[kt][2] = pkbf(y.x,y.y);
      }
      if (r1 < C_){
        float2 x = *(const float2*)(E0 + (long)r1*128 + k0);
        float2 y = *(const float2*)(E0 + (long)r1*128 + k0 + 8);
        aA[kt][1] = pkbf(x.x,x.y); aA[kt][3] = pkbf(y.x,y.y);
        x = *(const float2*)(E1 + (long)r1*128 + k0);
        y = *(const float2*)(E1 + (long)r1*128 + k0 + 8);
        aB[kt][1] = pkbf(x.x,x.y); aB[kt][3] = pkbf(y.x,y.y);
      }
    }
    const uint4* bp = (const uint4*)g_WT16;
    float pA0=0.f, pA1=0.f, pB0=0.f, pB1=0.f;
#pragma unroll
    for (int n2=0;n2<8;n2++){
      float cA0[4]={0.f,0.f,0.f,0.f}, cA1[4]={0.f,0.f,0.f,0.f};
      float cB0[4]={0.f,0.f,0.f,0.f}, cB1[4]={0.f,0.f,0.f,0.f};
#pragma unroll
      for (int kt=0;kt<8;kt++){
        uint4 bv = bp[(kt*8 + n2)*32 + lane];
        mma16(cA0, aA[kt][0],aA[kt][1],aA[kt][2],aA[kt][3], bv.x, bv.y);
        mma16(cA1, aA[kt][0],aA[kt][1],aA[kt][2],aA[kt][3], bv.z, bv.w);
        mma16(cB0, aB[kt][0],aB[kt][1],aB[kt][2],aB[kt][3], bv.x, bv.y);
        mma16(cB1, aB[kt][0],aB[kt][1],aB[kt][2],aB[kt][3], bv.z, bv.w);
      }
      {
        int j0 = (2*n2)*8 + 2*tig;
        float w0=w2t[j0], w1=w2t[j0+1];
        float c0=ctv[0][j0], c1=ctv[0][j0+1];
        pA0 += w0*fmaxf(c0+cA0[0],0.f) + w1*fmaxf(c1+cA0[1],0.f);
        pA1 += w0*fmaxf(c0+cA0[2],0.f) + w1*fmaxf(c1+cA0[3],0.f);
        c0=ctv[1][j0]; c1=ctv[1][j0+1];
        pB0 += w0*fmaxf(c0+cB0[0],0.f) + w1*fmaxf(c1+cB0[1],0.f);
        pB1 += w0*fmaxf(c0+cB0[2],0.f) + w1*fmaxf(c1+cB0[3],0.f);
      }
      {
        int j0 = (2*n2+1)*8 + 2*tig;
        float w0=w2t[j0], w1=w2t[j0+1];
        float c0=ctv[0][j0], c1=ctv[0][j0+1];
        pA0 += w0*fmaxf(c0+cA1[0],0.f) + w1*fmaxf(c1+cA1[1],0.f);
        pA1 += w0*fmaxf(c0+cA1[2],0.f) + w1*fmaxf(c1+cA1[3],0.f);
        c0=ctv[1][j0]; c1=ctv[1][j0+1];
        pB0 += w0*fmaxf(c0+cB1[0],0.f) + w1*fmaxf(c1+cB1[1],0.f);
        pB1 += w0*fmaxf(c0+cB1[2],0.f) + w1*fmaxf(c1+cB1[3],0.f);
      }
    }
    pA0 += __shfl_xor_sync(0xffffffffu,pA0,1); pA0 += __shfl_xor_sync(0xffffffffu,pA0,2);
    pA1 += __shfl_xor_sync(0xffffffffu,pA1,1); pA1 += __shfl_xor_sync(0xffffffffu,pA1,2);
    pB0 += __shfl_xor_sync(0xffffffffu,pB0,1); pB0 += __shfl_xor_sync(0xffffffffu,pB0,2);
    pB1 += __shfl_xor_sync(0xffffffffu,pB1,1); pB1 += __shfl_xor_sync(0xffffffffu,pB1,2);
    if (tig==0){
      if (r0 < C_){ sco[0][1][r0] = (pA0 + bt2[0]) / Tt; sco[1][1][r0] = (pB0 + bt2[0]) / Tt; }
      if (r1 < C_){ sco[0][1][r1] = (pA1 + bt2[0]) / Tt; sco[1][1][r1] = (pB1 + bt2[0]) / Tt; }
    }
  }
  // ---- id pass: K=64 ----
  {
    const float* E0 = cide + (long)bA*C_*64;
    const float* E1 = cide + (long)bB*C_*64;
    unsigned aA[4][4], aB[4][4];
#pragma unroll
    for (int kt=0;kt<4;kt++){
      const int k0 = kt*16 + tig*2;
      aA[kt][0]=0u; aA[kt][1]=0u; aA[kt][2]=0u; aA[kt][3]=0u;
      aB[kt][0]=0u; aB[kt][1]=0u; aB[kt][2]=0u; aB[kt][3]=0u;
      if (r0 < C_){
        float2 x = *(const float2*)(E0 + (long)r0*64 + k0);
        float2 y = *(const float2*)(E0 + (long)r0*64 + k0 + 8);
        aA[kt][0] = pkbf(x.x,x.y); aA[kt][2] = pkbf(y.x,y.y);
        x = *(const float2*)(E1 + (long)r0*64 + k0);
        y = *(const float2*)(E1 + (long)r0*64 + k0 + 8);
        aB[kt][0] = pkbf(x.x,x.y); aB[kt][2] = pkbf(y.x,y.y);
      }
      if (r1 < C_){
        float2 x = *(const float2*)(E0 + (long)r1*64 + k0);
        float2 y = *(const float2*)(E0 + (long)r1*64 + k0 + 8);
        aA[kt][1] = pkbf(x.x,x.y); aA[kt][3] = pkbf(y.x,y.y);
        x = *(const float2*)(E1 + (long)r1*64 + k0);
        y = *(const float2*)(E1 + (long)r1*64 + k0 + 8);
        aB[kt][1] = pkbf(x.x,x.y); aB[kt][3] = pkbf(y.x,y.y);
      }
    }
    const uint4* bp = (const uint4*)g_WI16;
    float pA0=0.f, pA1=0.f, pB0=0.f, pB1=0.f;
#pragma unroll
    for (int n2=0;n2<8;n2++){
      float cA0[4]={0.f,0.f,0.f,0.f}, cA1[4]={0.f,0.f,0.f,0.f};
      float cB0[4]={0.f,0.f,0.f,0.f}, cB1[4]={0.f,0.f,0.f,0.f};
#pragma unroll
      for (int kt=0;kt<4;kt++){
        uint4 bv = bp[(kt*8 + n2)*32 + lane];
        mma16(cA0, aA[kt][0],aA[kt][1],aA[kt][2],aA[kt][3], bv.x, bv.y);
        mma16(cA1, aA[kt][0],aA[kt][1],aA[kt][2],aA[kt][3], bv.z, bv.w);
        mma16(cB0, aB[kt][0],aB[kt][1],aB[kt][2],aB[kt][3], bv.x, bv.y);
        mma16(cB1, aB[kt][0],aB[kt][1],aB[kt][2],aB[kt][3], bv.z, bv.w);
      }
      {
        int j0 = (2*n2)*8 + 2*tig;
        float w0=w2i[j0], w1=w2i[j0+1];
        float c0=civ[0][j0], c1=civ[0][j0+1];
        pA0 += w0*fmaxf(c0+cA0[0],0.f) + w1*fmaxf(c1+cA0[1],0.f);
        pA1 += w0*fmaxf(c0+cA0[2],0.f) + w1*fmaxf(c1+cA0[3],0.f);
        c0=civ[1][j0]; c1=civ[1][j0+1];
        pB0 += w0*fmaxf(c0+cB0[0],0.f) + w1*fmaxf(c1+cB0[1],0.f);
        pB1 += w0*fmaxf(c0+cB0[2],0.f) + w1*fmaxf(c1+cB0[3],0.f);
      }
      {
        int j0 = (2*n2+1)*8 + 2*tig;
        float w0=w2i[j0], w1=w2i[j0+1];
        float c0=civ[0][j0], c1=civ[0][j0+1];
        pA0 += w0*fmaxf(c0+cA1[0],0.f) + w1*fmaxf(c1+cA1[1],0.f);
        pA1 += w0*fmaxf(c0+cA1[2],0.f) + w1*fmaxf(c1+cA1[3],0.f);
        c0=civ[1][j0]; c1=civ[1][j0+1];
        pB0 += w0*fmaxf(c0+cB1[0],0.f) + w1*fmaxf(c1+cB1[1],0.f);
        pB1 += w0*fmaxf(c0+cB1[2],0.f) + w1*fmaxf(c1+cB1[3],0.f);
      }
    }
    pA0 += __shfl_xor_sync(0xffffffffu,pA0,1); pA0 += __shfl_xor_sync(0xffffffffu,pA0,2);
    pA1 += __shfl_xor_sync(0xffffffffu,pA1,1); pA1 += __shfl_xor_sync(0xffffffffu,pA1,2);
    pB0 += __shfl_xor_sync(0xffffffffu,pB0,1); pB0 += __shfl_xor_sync(0xffffffffu,pB0,2);
    pB1 += __shfl_xor_sync(0xffffffffu,pB1,1); pB1 += __shfl_xor_sync(0xffffffffu,pB1,2);
    if (tig==0){
      if (r0 < C_){ sco[0][2][r0] = (pA0 + bi2[0]) / Ti; sco[1][2][r0] = (pB0 + bi2[0]) / Ti; }
      if (r1 < C_){ sco[0][2][r1] = (pA1 + bi2[0]) / Ti; sco[1][2][r1] = (pB1 + bi2[0]) / Ti; }
    }
  }
  __syncthreads();

  // 6 softmaxes: warp w<6 handles (batch = w/3, channel = w%3)
  if (warp < 6){
    int bs = warp/3, chn = warp%3;
    float m = -1e30f;
    for (int q=lane;q<C_;q+=32) m = fmaxf(m, sco[bs][chn][q]);
    m = wmax(m);
    float s = 0.f;
    for (int q=lane;q<C_;q+=32) s += __expf(sco[bs][chn][q]-m);
    s = wsum(s);
    if (lane==0){ mx3[bs][chn]=m; inv3[bs][chn]=1.f/s; }
  }
  __syncthreads();
  if (tid < 100){
    const float a0=g_AL[bA*3], a1=g_AL[bA*3+1], a2=g_AL[bA*3+2];
    mixv[0][tid] = 0.01f
      + a0*__expf(sco[0][0][tid]-mx3[0][0])*inv3[0][0]
      + a1*__expf(sco[0][1][tid]-mx3[0][1])*inv3[0][1]
      + a2*__expf(sco[0][2][tid]-mx3[0][2])*inv3[0][2];
  } else if (tid >= 128 && tid < 228){
    int t = tid-128;
    const float a0=g_AL[bB*3], a1=g_AL[bB*3+1], a2=g_AL[bB*3+2];
    mixv[1][t] = 0.01f
      + a0*__expf(sco[1][0][t]-mx3[1][0])*inv3[1][0]
      + a1*__expf(sco[1][1][t]-mx3[1][1])*inv3[1][1]
      + a2*__expf(sco[1][2][t]-mx3[1][2])*inv3[1][2];
  }
  __syncthreads();
  if (warp < 2){
    float s = 0.f;
    for (int q=lane;q<C_;q+=32) s += mixv[warp][q];
    s = wsum(s);
    if (lane==0) sS[warp] = 1.f/s;
  }
  __syncthreads();
  if (tid < 100) out[(long)bA*C_ + tid] = mixv[0][tid]*sS[0];
  else if (tid >= 128 && tid < 228) out[(long)bB*C_ + (tid-128)] = mixv[1][tid-128]*sS[1];
}

extern "C" void kernel_launch(void* const* d_in, const int* in_sizes, int n_in,
                              void* d_out, int out_size) {
  const int*   sitems = (const int*)  d_in[0];
  const float* ide    = (const float*)d_in[1];
  const float* txe    = (const float*)d_in[2];
  const int*   lens   = (const int*)  d_in[3];
  const int*   cids   = (const int*)  d_in[4];
  const float* cide   = (const float*)d_in[5];
  const float* ctxe   = (const float*)d_in[6];
  const float* co     = (const float*)d_in[7];
  const float* Wih    = (const float*)d_in[8];
  const float* Whh    = (const float*)d_in[9];
  const float* bih    = (const float*)d_in[10];
  const float* bhh    = (const float*)d_in[11];
  const float* Wt1    = (const float*)d_in[12];
  const float* bt1    = (const float*)d_in[13];
  const float* Wt2    = (const float*)d_in[14];
  const float* bt2    = (const float*)d_in[15];
  const float* Wi1    = (const float*)d_in[16];
  const float* bi1    = (const float*)d_in[17];
  const float* Wi2    = (const float*)d_in[18];
  const float* bi2    = (const float*)d_in[19];
  const float* Wa1    = (const float*)d_in[20];
  const float* ba1    = (const float*)d_in[21];
  const float* Wa2    = (const float*)d_in[22];
  const float* ba2    = (const float*)d_in[23];
  // d_in[24] = Wstab: unused (P_stable is uniform = 1/C exactly)
  const float* betac  = (const float*)d_in[25];
  const float* lTc    = (const float*)d_in[26];
  const float* lTt    = (const float*)d_in[27];
  const float* lTi    = (const float*)d_in[28];
  float* out = (float*)d_out;

  const int GRU_SMEM = (49152 + 2048 + 384 + 128 + 128 + 64 + 192 + 4) * 4;
  cudaFuncSetAttribute(k_gruall, cudaFuncAttributeMaxDynamicSharedMemorySize, GRU_SMEM);

  const int WPREP_N = 73728+49152+32768+24576+8192+8192+4096;
  k_wprep<<<(WPREP_N+255)/256, 256>>>(Wih, Whh, Wt1, Wi1, Wa1);
  k_ig<<<dim3(80,3), 256>>>(ide, txe, lens, bih);
  k_gruall<<<128, 256, GRU_SMEM>>>(bhh, ide, txe, lens, sitems,
                                   bt1, bi1, ba1, Wa2, ba2);
  k_score<<<B_/2, 256>>>(ctxe, cide, cids, co, Wt2, bt2, Wi2, bi2,
                         betac, lTc, lTt, lTi, out);
}